// round 3
// baseline (speedup 1.0000x reference)
#include <cuda_runtime.h>
#include <math.h>

// Problem constants (fixed by the dataset; runtime values derived from sizes
// are used for loop bounds, these only size static scratch).
#define MAX_NODES 20000

// Scratch accumulators (no allocation allowed -> __device__ globals).
// A_v: [N][32][3], A_d (symmetric, 6 unique): [N][32][6]
__device__ float g_Av[MAX_NODES * 32 * 3];
__device__ float g_Ad[MAX_NODES * 32 * 6];

// ---------------------------------------------------------------------------
// Zero the accumulators (A_a region of d_out + scratch).
// ---------------------------------------------------------------------------
__global__ void zero_kernel(float* __restrict__ out_aa, int n_aa, int n_av, int n_ad) {
    int i = blockIdx.x * blockDim.x + threadIdx.x;
    int stride = gridDim.x * blockDim.x;
    for (int k = i; k < n_aa; k += stride) out_aa[k] = 0.0f;
    for (int k = i; k < n_av; k += stride) g_Av[k] = 0.0f;
    for (int k = i; k < n_ad; k += stride) g_Ad[k] = 0.0f;
}

// ---------------------------------------------------------------------------
// Per-edge kernel: radial MLP -> rad[32], rs[3]; scatter rank-1 tensor
// moments with atomics. One thread = one edge.
// ---------------------------------------------------------------------------
__global__ __launch_bounds__(128)
void edge_kernel(const float* __restrict__ r_ij,
                 const float* __restrict__ w_rad,  const float* __restrict__ b_rad,
                 const float* __restrict__ w_direct,
                 const float* __restrict__ w1, const float* __restrict__ b1,
                 const float* __restrict__ w2, const float* __restrict__ b2,
                 const float* __restrict__ w3, const float* __restrict__ b3,
                 const int*   __restrict__ edges_src,
                 float* __restrict__ out_aa,
                 int E)
{
    __shared__ float s_wrad[8 * 32];
    __shared__ float s_brad[32];
    __shared__ float s_wdir[32 * 32];
    __shared__ float s_w1[32 * 64];
    __shared__ float s_b1[64];
    __shared__ float s_w2[64 * 64];
    __shared__ float s_b2[64];
    __shared__ float s_w3[64 * 32];
    __shared__ float s_b3[32];

    // Cooperative weight staging
    for (int i = threadIdx.x; i < 8 * 32;  i += blockDim.x) s_wrad[i] = w_rad[i];
    for (int i = threadIdx.x; i < 32;      i += blockDim.x) s_brad[i] = b_rad[i];
    for (int i = threadIdx.x; i < 32 * 32; i += blockDim.x) s_wdir[i] = w_direct[i];
    for (int i = threadIdx.x; i < 32 * 64; i += blockDim.x) s_w1[i]   = w1[i];
    for (int i = threadIdx.x; i < 64;      i += blockDim.x) s_b1[i]   = b1[i];
    for (int i = threadIdx.x; i < 64 * 64; i += blockDim.x) s_w2[i]   = w2[i];
    for (int i = threadIdx.x; i < 64;      i += blockDim.x) s_b2[i]   = b2[i];
    for (int i = threadIdx.x; i < 64 * 32; i += blockDim.x) s_w3[i]   = w3[i];
    for (int i = threadIdx.x; i < 32;      i += blockDim.x) s_b3[i]   = b3[i];
    __syncthreads();

    int e = blockIdx.x * blockDim.x + threadIdx.x;
    if (e >= E) return;

    float rx = r_ij[3 * e + 0];
    float ry = r_ij[3 * e + 1];
    float rz = r_ij[3 * e + 2];

    // 8 Gaussian radial basis functions; centers k/7, width 1/8
    float d = sqrtf(rx * rx + ry * ry + rz * rz);
    float enc[8];
    #pragma unroll
    for (int k = 0; k < 8; k++) {
        float t = (d - (float)k * (1.0f / 7.0f)) * 8.0f;
        enc[k] = __expf(-t * t);
    }

    // h = enc @ w_rad + b_rad
    float h[32];
    #pragma unroll
    for (int j = 0; j < 32; j++) h[j] = s_brad[j];
    #pragma unroll
    for (int k = 0; k < 8; k++) {
        float ek = enc[k];
        #pragma unroll
        for (int j = 0; j < 32; j++) h[j] = fmaf(ek, s_wrad[k * 32 + j], h[j]);
    }

    // rad = h @ w_direct  (direct path first, so h can die before t2)
    float rad[32];
    #pragma unroll
    for (int j = 0; j < 32; j++) rad[j] = 0.0f;
    #pragma unroll
    for (int k = 0; k < 32; k++) {
        float hk = h[k];
        #pragma unroll
        for (int j = 0; j < 32; j++) rad[j] = fmaf(hk, s_wdir[k * 32 + j], rad[j]);
    }

    // t1 = lrelu(h @ w1 + b1)
    float t1[64];
    #pragma unroll
    for (int j = 0; j < 64; j++) t1[j] = s_b1[j];
    #pragma unroll
    for (int k = 0; k < 32; k++) {
        float hk = h[k];
        #pragma unroll
        for (int j = 0; j < 64; j++) t1[j] = fmaf(hk, s_w1[k * 64 + j], t1[j]);
    }
    #pragma unroll
    for (int j = 0; j < 64; j++) t1[j] = t1[j] > 0.0f ? t1[j] : 0.1f * t1[j];

    // t2 = lrelu(t1 @ w2 + b2)
    float t2[64];
    #pragma unroll
    for (int j = 0; j < 64; j++) t2[j] = s_b2[j];
    #pragma unroll
    for (int k = 0; k < 64; k++) {
        float tk = t1[k];
        #pragma unroll
        for (int j = 0; j < 64; j++) t2[j] = fmaf(tk, s_w2[k * 64 + j], t2[j]);
    }
    #pragma unroll
    for (int j = 0; j < 64; j++) t2[j] = t2[j] > 0.0f ? t2[j] : 0.1f * t2[j];

    // rad += t2 @ w3 + b3
    #pragma unroll
    for (int j = 0; j < 32; j++) rad[j] += s_b3[j];
    #pragma unroll
    for (int k = 0; k < 64; k++) {
        float tk = t2[k];
        #pragma unroll
        for (int j = 0; j < 32; j++) rad[j] = fmaf(tk, s_w3[k * 32 + j], rad[j]);
    }

    // rs = tens_sigmoid(r * 7)
    float sx = rx * 7.0f, sy = ry * 7.0f, sz = rz * 7.0f;
    float inv = rsqrtf(1.0f + sx * sx + sy * sy + sz * sz);
    float X = sx * inv, Y = sy * inv, Z = sz * inv;

    float m0 = X * X, m1 = Y * Y, m2 = Z * Z;
    float m3 = X * Y, m4 = X * Z, m5 = Y * Z;

    int n = edges_src[e];
    float* aa = out_aa + n * 32;
    float* av = g_Av + n * 96;
    float* ad = g_Ad + n * 192;

    #pragma unroll
    for (int a = 0; a < 32; a++) {
        float ra = rad[a];
        atomicAdd(aa + a, ra);
        atomicAdd(av + a * 3 + 0, ra * X);
        atomicAdd(av + a * 3 + 1, ra * Y);
        atomicAdd(av + a * 3 + 2, ra * Z);
        atomicAdd(ad + a * 6 + 0, ra * m0);
        atomicAdd(ad + a * 6 + 1, ra * m1);
        atomicAdd(ad + a * 6 + 2, ra * m2);
        atomicAdd(ad + a * 6 + 3, ra * m3);
        atomicAdd(ad + a * 6 + 4, ra * m4);
        atomicAdd(ad + a * 6 + 5, ra * m5);
    }
}

// ---------------------------------------------------------------------------
// Per-node kernel: contract A_v with w_v and A_d(sym) with w_d, write out_v /
// out_d. One warp per node; lane = channel.
// ---------------------------------------------------------------------------
__global__ __launch_bounds__(128)
void node_kernel(const float* __restrict__ w_v, const float* __restrict__ w_d,
                 float* __restrict__ out, int N)
{
    __shared__ float s_wv[32 * 32];
    __shared__ float s_wd[32 * 32];
    __shared__ float s_av[4][32][3];
    __shared__ float s_ad[4][32][6];

    for (int i = threadIdx.x; i < 32 * 32; i += blockDim.x) {
        s_wv[i] = w_v[i];
        s_wd[i] = w_d[i];
    }
    __syncthreads();

    int warp = threadIdx.x >> 5;
    int lane = threadIdx.x & 31;
    int n = blockIdx.x * 4 + warp;
    if (n >= N) return;

    // Stage this node's A_v / A_d tile (lane = a)
    #pragma unroll
    for (int c = 0; c < 3; c++) s_av[warp][lane][c] = g_Av[n * 96 + lane * 3 + c];
    #pragma unroll
    for (int s = 0; s < 6; s++) s_ad[warp][lane][s] = g_Ad[n * 192 + lane * 6 + s];
    __syncwarp();

    // lane = output channel (v for out_v, d for out_d)
    float ov0 = 0.f, ov1 = 0.f, ov2 = 0.f;
    float od[6] = {0.f, 0.f, 0.f, 0.f, 0.f, 0.f};
    #pragma unroll
    for (int a = 0; a < 32; a++) {
        float wv = s_wv[a * 32 + lane];
        float wd = s_wd[a * 32 + lane];
        ov0 = fmaf(wv, s_av[warp][a][0], ov0);
        ov1 = fmaf(wv, s_av[warp][a][1], ov1);
        ov2 = fmaf(wv, s_av[warp][a][2], ov2);
        #pragma unroll
        for (int s = 0; s < 6; s++) od[s] = fmaf(wd, s_ad[warp][a][s], od[s]);
    }

    // out_v: [N][32][3] at offset N*32
    float* pv = out + (size_t)N * 32 + (size_t)n * 96 + lane * 3;
    pv[0] = ov0; pv[1] = ov1; pv[2] = ov2;

    // out_d: [N][32][3][3] at offset N*32 + N*96
    // sym order od = [XX, YY, ZZ, XY, XZ, YZ]
    float* pd = out + (size_t)N * 32 + (size_t)N * 96 + (size_t)n * 288 + lane * 9;
    pd[0] = od[0]; pd[1] = od[3]; pd[2] = od[4];
    pd[3] = od[3]; pd[4] = od[1]; pd[5] = od[5];
    pd[6] = od[4]; pd[7] = od[5]; pd[8] = od[2];
}

// ---------------------------------------------------------------------------
// kernel_launch
// Inputs (metadata order):
//  0 r_ij [E,3] f32       1 w_rad [8,32]   2 b_rad [32]   3 w_direct [32,32]
//  4 w1 [32,64]  5 b1[64] 6 w2 [64,64] 7 b2[64] 8 w3 [64,32] 9 b3[32]
// 10 w_v [32,32] 11 w_d [32,32] 12 edges_src [E] i32  13 n_nodes (unused)
// Output: concat(A_a [N,32], out_v [N,32,3], out_d [N,32,3,3]) -> N*416 f32
// ---------------------------------------------------------------------------
extern "C" void kernel_launch(void* const* d_in, const int* in_sizes, int n_in,
                              void* d_out, int out_size) {
    const float* r_ij     = (const float*)d_in[0];
    const float* w_rad    = (const float*)d_in[1];
    const float* b_rad    = (const float*)d_in[2];
    const float* w_direct = (const float*)d_in[3];
    const float* w1       = (const float*)d_in[4];
    const float* b1       = (const float*)d_in[5];
    const float* w2       = (const float*)d_in[6];
    const float* b2       = (const float*)d_in[7];
    const float* w3       = (const float*)d_in[8];
    const float* b3       = (const float*)d_in[9];
    const float* w_v      = (const float*)d_in[10];
    const float* w_d      = (const float*)d_in[11];
    const int*   e_src    = (const int*)  d_in[12];

    int E = in_sizes[0] / 3;
    int N = out_size / 416;

    float* out = (float*)d_out;

    zero_kernel<<<1024, 256>>>(out, N * 32, N * 96, N * 192);

    edge_kernel<<<(E + 127) / 128, 128>>>(
        r_ij, w_rad, b_rad, w_direct, w1, b1, w2, b2, w3, b3,
        e_src, out, E);

    node_kernel<<<(N + 3) / 4, 128>>>(w_v, w_d, out, N);
}

// round 4
// speedup vs baseline: 1.7274x; 1.7274x over previous
#include <cuda_runtime.h>
#include <math.h>

#define MAX_NODES 20000
#define MAX_EDGES 640000

// Static scratch (no allocation allowed).
__device__ float  g_rad[MAX_EDGES * 32];   // per-edge rad vector [E][32]
__device__ float4 g_rs[MAX_EDGES];         // per-edge direction (X,Y,Z,_)
__device__ int    g_count[MAX_NODES];
__device__ int    g_offset[MAX_NODES];
__device__ int    g_cursor[MAX_NODES];
__device__ int    g_csr[MAX_EDGES];

// ---------------------------------------------------------------------------
// Zero the per-node counters.
// ---------------------------------------------------------------------------
__global__ void zero_counts_kernel(int N) {
    int i = blockIdx.x * blockDim.x + threadIdx.x;
    if (i < N) g_count[i] = 0;
}

// ---------------------------------------------------------------------------
// Histogram of edge source nodes.
// ---------------------------------------------------------------------------
__global__ void hist_kernel(const int* __restrict__ edges_src, int E) {
    int e = blockIdx.x * blockDim.x + threadIdx.x;
    if (e < E) atomicAdd(&g_count[edges_src[e]], 1);
}

// ---------------------------------------------------------------------------
// Single-block exclusive prefix scan of g_count -> g_offset (+ cursor copy).
// ---------------------------------------------------------------------------
__global__ void scan_kernel(int N) {
    __shared__ int tmp[1024];
    __shared__ int s_carry;
    int tid = threadIdx.x;
    if (tid == 0) s_carry = 0;
    __syncthreads();

    for (int base = 0; base < N; base += 1024) {
        int i = base + tid;
        int v = (i < N) ? g_count[i] : 0;
        tmp[tid] = v;
        __syncthreads();
        for (int off = 1; off < 1024; off <<= 1) {
            int t = (tid >= off) ? tmp[tid - off] : 0;
            __syncthreads();
            tmp[tid] += t;
            __syncthreads();
        }
        int excl = tmp[tid] - v + s_carry;
        if (i < N) { g_offset[i] = excl; g_cursor[i] = excl; }
        __syncthreads();
        if (tid == 1023) s_carry += tmp[1023];
        __syncthreads();
    }
}

// ---------------------------------------------------------------------------
// Fill CSR edge lists.
// ---------------------------------------------------------------------------
__global__ void fill_kernel(const int* __restrict__ edges_src, int E) {
    int e = blockIdx.x * blockDim.x + threadIdx.x;
    if (e < E) {
        int pos = atomicAdd(&g_cursor[edges_src[e]], 1);
        g_csr[pos] = e;
    }
}

// ---------------------------------------------------------------------------
// Per-edge kernel: radial MLP -> rad[32], rs[3]; STORE to scratch (no atomics)
// ---------------------------------------------------------------------------
__global__ __launch_bounds__(128)
void edge_kernel(const float* __restrict__ r_ij,
                 const float* __restrict__ w_rad,  const float* __restrict__ b_rad,
                 const float* __restrict__ w_direct,
                 const float* __restrict__ w1, const float* __restrict__ b1,
                 const float* __restrict__ w2, const float* __restrict__ b2,
                 const float* __restrict__ w3, const float* __restrict__ b3,
                 int E)
{
    __shared__ float s_wrad[8 * 32];
    __shared__ float s_brad[32];
    __shared__ float s_wdir[32 * 32];
    __shared__ float s_w1[32 * 64];
    __shared__ float s_b1[64];
    __shared__ float s_w2[64 * 64];
    __shared__ float s_b2[64];
    __shared__ float s_w3[64 * 32];
    __shared__ float s_b3[32];

    for (int i = threadIdx.x; i < 8 * 32;  i += blockDim.x) s_wrad[i] = w_rad[i];
    for (int i = threadIdx.x; i < 32;      i += blockDim.x) s_brad[i] = b_rad[i];
    for (int i = threadIdx.x; i < 32 * 32; i += blockDim.x) s_wdir[i] = w_direct[i];
    for (int i = threadIdx.x; i < 32 * 64; i += blockDim.x) s_w1[i]   = w1[i];
    for (int i = threadIdx.x; i < 64;      i += blockDim.x) s_b1[i]   = b1[i];
    for (int i = threadIdx.x; i < 64 * 64; i += blockDim.x) s_w2[i]   = w2[i];
    for (int i = threadIdx.x; i < 64;      i += blockDim.x) s_b2[i]   = b2[i];
    for (int i = threadIdx.x; i < 64 * 32; i += blockDim.x) s_w3[i]   = w3[i];
    for (int i = threadIdx.x; i < 32;      i += blockDim.x) s_b3[i]   = b3[i];
    __syncthreads();

    int e = blockIdx.x * blockDim.x + threadIdx.x;
    if (e >= E) return;

    float rx = r_ij[3 * e + 0];
    float ry = r_ij[3 * e + 1];
    float rz = r_ij[3 * e + 2];

    // 8 Gaussian RBFs; centers k/7, width 1/8
    float d = sqrtf(rx * rx + ry * ry + rz * rz);
    float enc[8];
    #pragma unroll
    for (int k = 0; k < 8; k++) {
        float t = (d - (float)k * (1.0f / 7.0f)) * 8.0f;
        enc[k] = __expf(-t * t);
    }

    // h = enc @ w_rad + b_rad
    float h[32];
    #pragma unroll
    for (int j = 0; j < 32; j++) h[j] = s_brad[j];
    #pragma unroll
    for (int k = 0; k < 8; k++) {
        float ek = enc[k];
        #pragma unroll
        for (int j = 0; j < 32; j++) h[j] = fmaf(ek, s_wrad[k * 32 + j], h[j]);
    }

    // rad = h @ w_direct
    float rad[32];
    #pragma unroll
    for (int j = 0; j < 32; j++) rad[j] = 0.0f;
    #pragma unroll
    for (int k = 0; k < 32; k++) {
        float hk = h[k];
        #pragma unroll
        for (int j = 0; j < 32; j++) rad[j] = fmaf(hk, s_wdir[k * 32 + j], rad[j]);
    }

    // t1 = lrelu(h @ w1 + b1)
    float t1[64];
    #pragma unroll
    for (int j = 0; j < 64; j++) t1[j] = s_b1[j];
    #pragma unroll
    for (int k = 0; k < 32; k++) {
        float hk = h[k];
        #pragma unroll
        for (int j = 0; j < 64; j++) t1[j] = fmaf(hk, s_w1[k * 64 + j], t1[j]);
    }
    #pragma unroll
    for (int j = 0; j < 64; j++) t1[j] = t1[j] > 0.0f ? t1[j] : 0.1f * t1[j];

    // t2 = lrelu(t1 @ w2 + b2)
    float t2[64];
    #pragma unroll
    for (int j = 0; j < 64; j++) t2[j] = s_b2[j];
    #pragma unroll
    for (int k = 0; k < 64; k++) {
        float tk = t1[k];
        #pragma unroll
        for (int j = 0; j < 64; j++) t2[j] = fmaf(tk, s_w2[k * 64 + j], t2[j]);
    }
    #pragma unroll
    for (int j = 0; j < 64; j++) t2[j] = t2[j] > 0.0f ? t2[j] : 0.1f * t2[j];

    // rad += t2 @ w3 + b3
    #pragma unroll
    for (int j = 0; j < 32; j++) rad[j] += s_b3[j];
    #pragma unroll
    for (int k = 0; k < 64; k++) {
        float tk = t2[k];
        #pragma unroll
        for (int j = 0; j < 32; j++) rad[j] = fmaf(tk, s_w3[k * 32 + j], rad[j]);
    }

    // rs = tens_sigmoid(r * 7)
    float sx = rx * 7.0f, sy = ry * 7.0f, sz = rz * 7.0f;
    float inv = rsqrtf(1.0f + sx * sx + sy * sy + sz * sz);
    g_rs[e] = make_float4(sx * inv, sy * inv, sz * inv, 0.0f);

    // store rad row (vectorized)
    float4* dst = (float4*)(g_rad + (size_t)e * 32);
    #pragma unroll
    for (int q = 0; q < 8; q++)
        dst[q] = make_float4(rad[4 * q], rad[4 * q + 1], rad[4 * q + 2], rad[4 * q + 3]);
}

// ---------------------------------------------------------------------------
// Per-node gather + output contraction. One warp per node, lane = channel a
// during gather, lane = output channel during the w_v/w_d contraction.
// ---------------------------------------------------------------------------
__global__ __launch_bounds__(256)
void node_kernel(const float* __restrict__ w_v, const float* __restrict__ w_d,
                 float* __restrict__ out, int N)
{
    __shared__ float s_wv[32 * 32];
    __shared__ float s_wd[32 * 32];
    __shared__ float s_t[8][32][9];   // per-warp staging: av[3] + ad[6]

    for (int i = threadIdx.x; i < 32 * 32; i += blockDim.x) {
        s_wv[i] = w_v[i];
        s_wd[i] = w_d[i];
    }
    __syncthreads();

    int warp = threadIdx.x >> 5;
    int lane = threadIdx.x & 31;
    int n = blockIdx.x * 8 + warp;
    if (n >= N) return;

    int beg = g_offset[n];
    int cnt = g_count[n];

    float aa = 0.f;
    float av0 = 0.f, av1 = 0.f, av2 = 0.f;
    float ad0 = 0.f, ad1 = 0.f, ad2 = 0.f, ad3 = 0.f, ad4 = 0.f, ad5 = 0.f;

    for (int t = 0; t < cnt; t++) {
        int e = g_csr[beg + t];
        float ra = __ldg(g_rad + (size_t)e * 32 + lane);   // coalesced 128B
        float4 rs = g_rs[e];                                // warp broadcast
        float X = rs.x, Y = rs.y, Z = rs.z;
        float tx = ra * X, ty = ra * Y, tz = ra * Z;
        aa  += ra;
        av0 += tx;  av1 += ty;  av2 += tz;
        ad0 = fmaf(tx, X, ad0);   // XX
        ad1 = fmaf(ty, Y, ad1);   // YY
        ad2 = fmaf(tz, Z, ad2);   // ZZ
        ad3 = fmaf(tx, Y, ad3);   // XY
        ad4 = fmaf(tx, Z, ad4);   // XZ
        ad5 = fmaf(ty, Z, ad5);   // YZ
    }

    // A_a straight to output (lane = a)
    out[(size_t)n * 32 + lane] = aa;

    // Stage moments for cross-lane contraction
    s_t[warp][lane][0] = av0;  s_t[warp][lane][1] = av1;  s_t[warp][lane][2] = av2;
    s_t[warp][lane][3] = ad0;  s_t[warp][lane][4] = ad1;  s_t[warp][lane][5] = ad2;
    s_t[warp][lane][6] = ad3;  s_t[warp][lane][7] = ad4;  s_t[warp][lane][8] = ad5;
    __syncwarp();

    // lane = output channel
    float ov0 = 0.f, ov1 = 0.f, ov2 = 0.f;
    float od[6] = {0.f, 0.f, 0.f, 0.f, 0.f, 0.f};
    #pragma unroll
    for (int a = 0; a < 32; a++) {
        float wv = s_wv[a * 32 + lane];
        float wd = s_wd[a * 32 + lane];
        ov0 = fmaf(wv, s_t[warp][a][0], ov0);
        ov1 = fmaf(wv, s_t[warp][a][1], ov1);
        ov2 = fmaf(wv, s_t[warp][a][2], ov2);
        #pragma unroll
        for (int s = 0; s < 6; s++) od[s] = fmaf(wd, s_t[warp][a][3 + s], od[s]);
    }

    // out_v: [N][32][3] at offset N*32
    float* pv = out + (size_t)N * 32 + (size_t)n * 96 + lane * 3;
    pv[0] = ov0; pv[1] = ov1; pv[2] = ov2;

    // out_d: [N][32][3][3] at offset N*32 + N*96 ; od = [XX,YY,ZZ,XY,XZ,YZ]
    float* pd = out + (size_t)N * 128 + (size_t)n * 288 + lane * 9;
    pd[0] = od[0]; pd[1] = od[3]; pd[2] = od[4];
    pd[3] = od[3]; pd[4] = od[1]; pd[5] = od[5];
    pd[6] = od[4]; pd[7] = od[5]; pd[8] = od[2];
}

// ---------------------------------------------------------------------------
// kernel_launch
// ---------------------------------------------------------------------------
extern "C" void kernel_launch(void* const* d_in, const int* in_sizes, int n_in,
                              void* d_out, int out_size) {
    const float* r_ij     = (const float*)d_in[0];
    const float* w_rad    = (const float*)d_in[1];
    const float* b_rad    = (const float*)d_in[2];
    const float* w_direct = (const float*)d_in[3];
    const float* w1       = (const float*)d_in[4];
    const float* b1       = (const float*)d_in[5];
    const float* w2       = (const float*)d_in[6];
    const float* b2       = (const float*)d_in[7];
    const float* w3       = (const float*)d_in[8];
    const float* b3       = (const float*)d_in[9];
    const float* w_v      = (const float*)d_in[10];
    const float* w_d      = (const float*)d_in[11];
    const int*   e_src    = (const int*)  d_in[12];

    int E = in_sizes[0] / 3;
    int N = out_size / 416;

    float* out = (float*)d_out;

    // CSR build
    zero_counts_kernel<<<(N + 255) / 256, 256>>>(N);
    hist_kernel<<<(E + 255) / 256, 256>>>(e_src, E);
    scan_kernel<<<1, 1024>>>(N);
    fill_kernel<<<(E + 255) / 256, 256>>>(e_src, E);

    // Per-edge MLP (stores rad/rs; no atomics)
    edge_kernel<<<(E + 127) / 128, 128>>>(
        r_ij, w_rad, b_rad, w_direct, w1, b1, w2, b2, w3, b3, E);

    // Per-node gather + contraction
    node_kernel<<<(N + 7) / 8, 256>>>(w_v, w_d, out, N);
}

// round 6
// speedup vs baseline: 2.7732x; 1.6054x over previous
#include <cuda_runtime.h>
#include <math.h>

#define MAX_NODES 20000
#define MAX_EDGES 640000

// Static scratch (no allocation allowed).
__device__ float  g_rad[MAX_EDGES * 32];   // per-edge rad vector [E][32]
__device__ float4 g_rs[MAX_EDGES];         // per-edge direction (X,Y,Z,_)
__device__ int    g_count[MAX_NODES];
__device__ int    g_offset[MAX_NODES];
__device__ int    g_cursor[MAX_NODES];
__device__ int    g_csr[MAX_EDGES];

// ---------------------------------------------------------------------------
// Packed f32x2 helpers (Blackwell FFMA2 — only reachable via PTX)
// ---------------------------------------------------------------------------
typedef unsigned long long u64;

__device__ __forceinline__ u64 pack2(float lo, float hi) {
    u64 r;
    asm("mov.b64 %0, {%1, %2};" : "=l"(r) : "f"(lo), "f"(hi));
    return r;
}
__device__ __forceinline__ void unpack2(u64 v, float& lo, float& hi) {
    asm("mov.b64 {%0, %1}, %2;" : "=f"(lo), "=f"(hi) : "l"(v));
}
#define FMA2(d, a, b, c) \
    asm("fma.rn.f32x2 %0, %1, %2, %3;" : "=l"(d) : "l"(a), "l"(b), "l"(c))

// ---------------------------------------------------------------------------
// Zero the per-node counters.
// ---------------------------------------------------------------------------
__global__ void zero_counts_kernel(int N) {
    int i = blockIdx.x * blockDim.x + threadIdx.x;
    if (i < N) g_count[i] = 0;
}

// ---------------------------------------------------------------------------
// Single-block exclusive prefix scan of g_count -> g_offset (+ cursor copy).
// Hierarchical warp-shuffle scan.
// ---------------------------------------------------------------------------
__global__ void scan_kernel(int N) {
    __shared__ int s_warp[32];
    __shared__ int s_carry;
    int tid = threadIdx.x;
    int lane = tid & 31;
    int wid = tid >> 5;
    if (tid == 0) s_carry = 0;
    __syncthreads();

    for (int base = 0; base < N; base += 1024) {
        int i = base + tid;
        int v = (i < N) ? g_count[i] : 0;
        // warp inclusive scan
        int x = v;
        #pragma unroll
        for (int off = 1; off < 32; off <<= 1) {
            int t = __shfl_up_sync(0xffffffffu, x, off);
            if (lane >= off) x += t;
        }
        if (lane == 31) s_warp[wid] = x;
        __syncthreads();
        if (wid == 0) {
            int w = s_warp[lane];
            #pragma unroll
            for (int off = 1; off < 32; off <<= 1) {
                int t = __shfl_up_sync(0xffffffffu, w, off);
                if (lane >= off) w += t;
            }
            s_warp[lane] = w;
        }
        __syncthreads();
        int warp_excl = (wid == 0) ? 0 : s_warp[wid - 1];
        int excl = x - v + warp_excl + s_carry;
        if (i < N) { g_offset[i] = excl; g_cursor[i] = excl; }
        __syncthreads();
        if (tid == 1023) s_carry += x + warp_excl - s_carry + s_carry - (x + warp_excl) + (x + warp_excl);
        // ^ equivalent to s_carry = s_carry + total; write plainly below instead
        if (tid == 1023) s_carry = excl + v;
        __syncthreads();
    }
}

// ---------------------------------------------------------------------------
// Fill CSR edge lists.
// ---------------------------------------------------------------------------
__global__ void fill_kernel(const int* __restrict__ edges_src, int E) {
    int e = blockIdx.x * blockDim.x + threadIdx.x;
    if (e < E) {
        int pos = atomicAdd(&g_cursor[edges_src[e]], 1);
        g_csr[pos] = e;
    }
}

// ---------------------------------------------------------------------------
// Per-edge kernel: radial MLP on packed f32x2 -> rad[32], rs[3]; stores to
// scratch. Also builds the degree histogram (fused, 1 atomic/edge).
// ---------------------------------------------------------------------------
__global__ __launch_bounds__(128)
void edge_kernel(const float* __restrict__ r_ij,
                 const float* __restrict__ w_rad,  const float* __restrict__ b_rad,
                 const float* __restrict__ w_direct,
                 const float* __restrict__ w1, const float* __restrict__ b1,
                 const float* __restrict__ w2, const float* __restrict__ b2,
                 const float* __restrict__ w3, const float* __restrict__ b3,
                 const int*   __restrict__ edges_src,
                 int E)
{
    __shared__ __align__(16) float s_wrad[8 * 32];
    __shared__ __align__(16) float s_brad[32];
    __shared__ __align__(16) float s_wdir[32 * 32];
    __shared__ __align__(16) float s_w1[32 * 64];
    __shared__ __align__(16) float s_b1[64];
    __shared__ __align__(16) float s_w2[64 * 64];
    __shared__ __align__(16) float s_b2[64];
    __shared__ __align__(16) float s_w3[64 * 32];
    __shared__ __align__(16) float s_b3[32];

    for (int i = threadIdx.x; i < 8 * 32;  i += blockDim.x) s_wrad[i] = w_rad[i];
    for (int i = threadIdx.x; i < 32;      i += blockDim.x) s_brad[i] = b_rad[i];
    for (int i = threadIdx.x; i < 32 * 32; i += blockDim.x) s_wdir[i] = w_direct[i];
    for (int i = threadIdx.x; i < 32 * 64; i += blockDim.x) s_w1[i]   = w1[i];
    for (int i = threadIdx.x; i < 64;      i += blockDim.x) s_b1[i]   = b1[i];
    for (int i = threadIdx.x; i < 64 * 64; i += blockDim.x) s_w2[i]   = w2[i];
    for (int i = threadIdx.x; i < 64;      i += blockDim.x) s_b2[i]   = b2[i];
    for (int i = threadIdx.x; i < 64 * 32; i += blockDim.x) s_w3[i]   = w3[i];
    for (int i = threadIdx.x; i < 32;      i += blockDim.x) s_b3[i]   = b3[i];
    __syncthreads();

    int e = blockIdx.x * blockDim.x + threadIdx.x;
    if (e >= E) return;

    // fused histogram
    atomicAdd(&g_count[edges_src[e]], 1);

    float rx = r_ij[3 * e + 0];
    float ry = r_ij[3 * e + 1];
    float rz = r_ij[3 * e + 2];

    // 8 Gaussian RBFs; centers k/7, width 1/8
    float d = sqrtf(rx * rx + ry * ry + rz * rz);
    float enc[8];
    #pragma unroll
    for (int k = 0; k < 8; k++) {
        float t = (d - (float)k * (1.0f / 7.0f)) * 8.0f;
        enc[k] = __expf(-t * t);
    }

    const u64* W_RAD = (const u64*)s_wrad;   // [8][16] pairs
    const u64* B_RAD = (const u64*)s_brad;
    const u64* W_DIR = (const u64*)s_wdir;   // [32][16]
    const u64* W_1   = (const u64*)s_w1;     // [32][32]
    const u64* B_1   = (const u64*)s_b1;
    const u64* W_2   = (const u64*)s_w2;     // [64][32]
    const u64* B_2   = (const u64*)s_b2;
    const u64* W_3   = (const u64*)s_w3;     // [64][16]
    const u64* B_3   = (const u64*)s_b3;

    // h = enc @ w_rad + b_rad  (16 packed accumulators)
    u64 h2[16];
    #pragma unroll
    for (int p = 0; p < 16; p++) h2[p] = B_RAD[p];
    #pragma unroll
    for (int k = 0; k < 8; k++) {
        u64 ek2 = pack2(enc[k], enc[k]);
        #pragma unroll
        for (int p = 0; p < 16; p++) FMA2(h2[p], ek2, W_RAD[k * 16 + p], h2[p]);
    }

    // rad = h @ w_direct ; t1 = h @ w1 + b1 (computed in one sweep over k)
    u64 rad2[16];
    #pragma unroll
    for (int p = 0; p < 16; p++) rad2[p] = 0;
    u64 t1[32];
    #pragma unroll
    for (int p = 0; p < 32; p++) t1[p] = B_1[p];

    #pragma unroll
    for (int kp = 0; kp < 16; kp++) {
        float hk0, hk1;
        unpack2(h2[kp], hk0, hk1);
        u64 a0 = pack2(hk0, hk0);
        u64 a1 = pack2(hk1, hk1);
        int k0 = 2 * kp, k1 = 2 * kp + 1;
        #pragma unroll
        for (int p = 0; p < 16; p++) {
            FMA2(rad2[p], a0, W_DIR[k0 * 16 + p], rad2[p]);
            FMA2(rad2[p], a1, W_DIR[k1 * 16 + p], rad2[p]);
        }
        #pragma unroll
        for (int p = 0; p < 32; p++) {
            FMA2(t1[p], a0, W_1[k0 * 32 + p], t1[p]);
            FMA2(t1[p], a1, W_1[k1 * 32 + p], t1[p]);
        }
    }
    // lrelu(t1)
    #pragma unroll
    for (int p = 0; p < 32; p++) {
        float lo, hi;
        unpack2(t1[p], lo, hi);
        lo = fmaxf(lo, 0.1f * lo);
        hi = fmaxf(hi, 0.1f * hi);
        t1[p] = pack2(lo, hi);
    }

    // t2 = lrelu(t1 @ w2 + b2)
    u64 t2[32];
    #pragma unroll
    for (int p = 0; p < 32; p++) t2[p] = B_2[p];
    #pragma unroll
    for (int kp = 0; kp < 32; kp++) {
        float k0v, k1v;
        unpack2(t1[kp], k0v, k1v);
        u64 a0 = pack2(k0v, k0v);
        u64 a1 = pack2(k1v, k1v);
        int k0 = 2 * kp, k1 = 2 * kp + 1;
        #pragma unroll
        for (int p = 0; p < 32; p++) {
            FMA2(t2[p], a0, W_2[k0 * 32 + p], t2[p]);
            FMA2(t2[p], a1, W_2[k1 * 32 + p], t2[p]);
        }
    }
    #pragma unroll
    for (int p = 0; p < 32; p++) {
        float lo, hi;
        unpack2(t2[p], lo, hi);
        lo = fmaxf(lo, 0.1f * lo);
        hi = fmaxf(hi, 0.1f * hi);
        t2[p] = pack2(lo, hi);
    }

    // rad += t2 @ w3 + b3
    u64 one2 = pack2(1.0f, 1.0f);
    #pragma unroll
    for (int p = 0; p < 16; p++) FMA2(rad2[p], one2, B_3[p], rad2[p]);
    #pragma unroll
    for (int kp = 0; kp < 32; kp++) {
        float k0v, k1v;
        unpack2(t2[kp], k0v, k1v);
        u64 a0 = pack2(k0v, k0v);
        u64 a1 = pack2(k1v, k1v);
        int k0 = 2 * kp, k1 = 2 * kp + 1;
        #pragma unroll
        for (int p = 0; p < 16; p++) {
            FMA2(rad2[p], a0, W_3[k0 * 16 + p], rad2[p]);
            FMA2(rad2[p], a1, W_3[k1 * 16 + p], rad2[p]);
        }
    }

    // rs = tens_sigmoid(r * 7)
    float sx = rx * 7.0f, sy = ry * 7.0f, sz = rz * 7.0f;
    float inv = rsqrtf(1.0f + sx * sx + sy * sy + sz * sz);
    g_rs[e] = make_float4(sx * inv, sy * inv, sz * inv, 0.0f);

    // store rad row (128-bit stores)
    ulonglong2* dst = (ulonglong2*)(g_rad + (size_t)e * 32);
    #pragma unroll
    for (int q = 0; q < 8; q++)
        dst[q] = make_ulonglong2(rad2[2 * q], rad2[2 * q + 1]);
}

// ---------------------------------------------------------------------------
// Per-node gather + output contraction. One warp per node, lane = channel a
// during gather; lane = output channel during the w_v/w_d contraction.
// CSR IDs read coalesced in chunks of 32 and broadcast via shuffle.
// ---------------------------------------------------------------------------
__global__ __launch_bounds__(256)
void node_kernel(const float* __restrict__ w_v, const float* __restrict__ w_d,
                 float* __restrict__ out, int N)
{
    __shared__ float s_wv[32 * 32];
    __shared__ float s_wd[32 * 32];
    __shared__ float s_t[8][32][9];   // per-warp staging: av[3] + ad[6]

    for (int i = threadIdx.x; i < 32 * 32; i += blockDim.x) {
        s_wv[i] = w_v[i];
        s_wd[i] = w_d[i];
    }
    __syncthreads();

    int warp = threadIdx.x >> 5;
    int lane = threadIdx.x & 31;
    int n = blockIdx.x * 8 + warp;
    if (n >= N) return;

    int beg = g_offset[n];
    int cnt = g_count[n];

    float aa = 0.f;
    float av0 = 0.f, av1 = 0.f, av2 = 0.f;
    float ad0 = 0.f, ad1 = 0.f, ad2 = 0.f, ad3 = 0.f, ad4 = 0.f, ad5 = 0.f;

    for (int t0 = 0; t0 < cnt; t0 += 32) {
        int m = cnt - t0; if (m > 32) m = 32;
        int eid = (t0 + lane < cnt) ? g_csr[beg + t0 + lane] : 0;  // coalesced
        #pragma unroll 4
        for (int i = 0; i < m; i++) {
            int e = __shfl_sync(0xffffffffu, eid, i);
            float ra = __ldg(g_rad + (size_t)e * 32 + lane);   // coalesced 128B
            float4 rs = g_rs[e];                                // broadcast
            float X = rs.x, Y = rs.y, Z = rs.z;
            float tx = ra * X, ty = ra * Y, tz = ra * Z;
            aa  += ra;
            av0 += tx;  av1 += ty;  av2 += tz;
            ad0 = fmaf(tx, X, ad0);
            ad1 = fmaf(ty, Y, ad1);
            ad2 = fmaf(tz, Z, ad2);
            ad3 = fmaf(tx, Y, ad3);
            ad4 = fmaf(tx, Z, ad4);
            ad5 = fmaf(ty, Z, ad5);
        }
    }

    // A_a straight to output (lane = a)
    out[(size_t)n * 32 + lane] = aa;

    // Stage moments for cross-lane contraction
    s_t[warp][lane][0] = av0;  s_t[warp][lane][1] = av1;  s_t[warp][lane][2] = av2;
    s_t[warp][lane][3] = ad0;  s_t[warp][lane][4] = ad1;  s_t[warp][lane][5] = ad2;
    s_t[warp][lane][6] = ad3;  s_t[warp][lane][7] = ad4;  s_t[warp][lane][8] = ad5;
    __syncwarp();

    // lane = output channel
    float ov0 = 0.f, ov1 = 0.f, ov2 = 0.f;
    float od[6] = {0.f, 0.f, 0.f, 0.f, 0.f, 0.f};
    #pragma unroll
    for (int a = 0; a < 32; a++) {
        float wv = s_wv[a * 32 + lane];
        float wd = s_wd[a * 32 + lane];
        ov0 = fmaf(wv, s_t[warp][a][0], ov0);
        ov1 = fmaf(wv, s_t[warp][a][1], ov1);
        ov2 = fmaf(wv, s_t[warp][a][2], ov2);
        #pragma unroll
        for (int s = 0; s < 6; s++) od[s] = fmaf(wd, s_t[warp][a][3 + s], od[s]);
    }

    // out_v: [N][32][3] at offset N*32
    float* pv = out + (size_t)N * 32 + (size_t)n * 96 + lane * 3;
    pv[0] = ov0; pv[1] = ov1; pv[2] = ov2;

    // out_d: [N][32][3][3] at offset N*128 ; od = [XX,YY,ZZ,XY,XZ,YZ]
    float* pd = out + (size_t)N * 128 + (size_t)n * 288 + lane * 9;
    pd[0] = od[0]; pd[1] = od[3]; pd[2] = od[4];
    pd[3] = od[3]; pd[4] = od[1]; pd[5] = od[5];
    pd[6] = od[4]; pd[7] = od[5]; pd[8] = od[2];
}

// ---------------------------------------------------------------------------
// kernel_launch
// ---------------------------------------------------------------------------
extern "C" void kernel_launch(void* const* d_in, const int* in_sizes, int n_in,
                              void* d_out, int out_size) {
    const float* r_ij     = (const float*)d_in[0];
    const float* w_rad    = (const float*)d_in[1];
    const float* b_rad    = (const float*)d_in[2];
    const float* w_direct = (const float*)d_in[3];
    const float* w1       = (const float*)d_in[4];
    const float* b1       = (const float*)d_in[5];
    const float* w2       = (const float*)d_in[6];
    const float* b2       = (const float*)d_in[7];
    const float* w3       = (const float*)d_in[8];
    const float* b3       = (const float*)d_in[9];
    const float* w_v      = (const float*)d_in[10];
    const float* w_d      = (const float*)d_in[11];
    const int*   e_src    = (const int*)  d_in[12];

    int E = in_sizes[0] / 3;
    int N = out_size / 416;

    float* out = (float*)d_out;

    zero_counts_kernel<<<(N + 255) / 256, 256>>>(N);

    // Per-edge MLP (FFMA2) + fused degree histogram
    edge_kernel<<<(E + 127) / 128, 128>>>(
        r_ij, w_rad, b_rad, w_direct, w1, b1, w2, b2, w3, b3, e_src, E);

    scan_kernel<<<1, 1024>>>(N);
    fill_kernel<<<(E + 255) / 256, 256>>>(e_src, E);

    // Per-node gather + contraction
    node_kernel<<<(N + 7) / 8, 256>>>(w_v, w_d, out, N);
}

// round 7
// speedup vs baseline: 9.1962x; 3.3161x over previous
#include <cuda_runtime.h>
#include <math.h>

#define MAX_NODES 20000
#define MAX_EDGES 640000
#define TABN      65536
#define DMAX      2.0f
// index scale: (TABN-1)/DMAX
#define TSCALE    32767.5f

// Static scratch (no allocation allowed).
__device__ float  g_table[TABN * 32];     // rad = F(d) lookup, 8MB (L2-resident)
__device__ float4 g_rs[MAX_EDGES];        // per-edge (X, Y, Z, d)
__device__ int    g_count[MAX_NODES];
__device__ int    g_offset[MAX_NODES];
__device__ int    g_cursor[MAX_NODES];
__device__ int    g_csr[MAX_EDGES];

// ---------------------------------------------------------------------------
// Packed f32x2 helpers (Blackwell FFMA2 — only reachable via PTX)
// ---------------------------------------------------------------------------
typedef unsigned long long u64;

__device__ __forceinline__ u64 pack2(float lo, float hi) {
    u64 r;
    asm("mov.b64 %0, {%1, %2};" : "=l"(r) : "f"(lo), "f"(hi));
    return r;
}
__device__ __forceinline__ void unpack2(u64 v, float& lo, float& hi) {
    asm("mov.b64 {%0, %1}, %2;" : "=f"(lo), "=f"(hi) : "l"(v));
}
#define FMA2(d, a, b, c) \
    asm("fma.rn.f32x2 %0, %1, %2, %3;" : "=l"(d) : "l"(a), "l"(b), "l"(c))

// ---------------------------------------------------------------------------
// Zero the per-node counters.
// ---------------------------------------------------------------------------
__global__ void zero_counts_kernel(int N) {
    int i = blockIdx.x * blockDim.x + threadIdx.x;
    if (i < N) g_count[i] = 0;
}

// ---------------------------------------------------------------------------
// Per-edge prep: d, rs -> g_rs; degree histogram (fused).
// ---------------------------------------------------------------------------
__global__ void prep_kernel(const float* __restrict__ r_ij,
                            const int* __restrict__ edges_src, int E) {
    int e = blockIdx.x * blockDim.x + threadIdx.x;
    if (e >= E) return;
    atomicAdd(&g_count[edges_src[e]], 1);
    float rx = r_ij[3 * e + 0];
    float ry = r_ij[3 * e + 1];
    float rz = r_ij[3 * e + 2];
    float d2 = rx * rx + ry * ry + rz * rz;
    float d  = sqrtf(d2);
    // rs = tens_sigmoid(r * 7): r*7 / sqrt(1 + 49*d2)
    float inv = rsqrtf(1.0f + 49.0f * d2) * 7.0f;
    g_rs[e] = make_float4(rx * inv, ry * inv, rz * inv, d);
}

// ---------------------------------------------------------------------------
// Single-block exclusive prefix scan of g_count -> g_offset (+ cursor copy).
// ---------------------------------------------------------------------------
__global__ void scan_kernel(int N) {
    __shared__ int s_warp[32];
    __shared__ int s_carry;
    int tid = threadIdx.x;
    int lane = tid & 31;
    int wid = tid >> 5;
    if (tid == 0) s_carry = 0;
    __syncthreads();

    for (int base = 0; base < N; base += 1024) {
        int i = base + tid;
        int v = (i < N) ? g_count[i] : 0;
        int x = v;
        #pragma unroll
        for (int off = 1; off < 32; off <<= 1) {
            int t = __shfl_up_sync(0xffffffffu, x, off);
            if (lane >= off) x += t;
        }
        if (lane == 31) s_warp[wid] = x;
        __syncthreads();
        if (wid == 0) {
            int w = s_warp[lane];
            #pragma unroll
            for (int off = 1; off < 32; off <<= 1) {
                int t = __shfl_up_sync(0xffffffffu, w, off);
                if (lane >= off) w += t;
            }
            s_warp[lane] = w;
        }
        __syncthreads();
        int warp_excl = (wid == 0) ? 0 : s_warp[wid - 1];
        int excl = x - v + warp_excl + s_carry;
        if (i < N) { g_offset[i] = excl; g_cursor[i] = excl; }
        __syncthreads();
        if (tid == 1023) s_carry = excl + v;
        __syncthreads();
    }
}

// ---------------------------------------------------------------------------
// Fill CSR edge lists.
// ---------------------------------------------------------------------------
__global__ void fill_kernel(const int* __restrict__ edges_src, int E) {
    int e = blockIdx.x * blockDim.x + threadIdx.x;
    if (e < E) {
        int pos = atomicAdd(&g_cursor[edges_src[e]], 1);
        g_csr[pos] = e;
    }
}

// ---------------------------------------------------------------------------
// Table builder: rad = F(d) for TABN samples of d in [0, DMAX].
// Full radial MLP on packed f32x2 (one thread = one sample).
// ---------------------------------------------------------------------------
__global__ __launch_bounds__(128)
void table_kernel(const float* __restrict__ w_rad,  const float* __restrict__ b_rad,
                  const float* __restrict__ w_direct,
                  const float* __restrict__ w1, const float* __restrict__ b1,
                  const float* __restrict__ w2, const float* __restrict__ b2,
                  const float* __restrict__ w3, const float* __restrict__ b3)
{
    __shared__ __align__(16) float s_wrad[8 * 32];
    __shared__ __align__(16) float s_brad[32];
    __shared__ __align__(16) float s_wdir[32 * 32];
    __shared__ __align__(16) float s_w1[32 * 64];
    __shared__ __align__(16) float s_b1[64];
    __shared__ __align__(16) float s_w2[64 * 64];
    __shared__ __align__(16) float s_b2[64];
    __shared__ __align__(16) float s_w3[64 * 32];
    __shared__ __align__(16) float s_b3[32];

    for (int i = threadIdx.x; i < 8 * 32;  i += blockDim.x) s_wrad[i] = w_rad[i];
    for (int i = threadIdx.x; i < 32;      i += blockDim.x) s_brad[i] = b_rad[i];
    for (int i = threadIdx.x; i < 32 * 32; i += blockDim.x) s_wdir[i] = w_direct[i];
    for (int i = threadIdx.x; i < 32 * 64; i += blockDim.x) s_w1[i]   = w1[i];
    for (int i = threadIdx.x; i < 64;      i += blockDim.x) s_b1[i]   = b1[i];
    for (int i = threadIdx.x; i < 64 * 64; i += blockDim.x) s_w2[i]   = w2[i];
    for (int i = threadIdx.x; i < 64;      i += blockDim.x) s_b2[i]   = b2[i];
    for (int i = threadIdx.x; i < 64 * 32; i += blockDim.x) s_w3[i]   = w3[i];
    for (int i = threadIdx.x; i < 32;      i += blockDim.x) s_b3[i]   = b3[i];
    __syncthreads();

    int t = blockIdx.x * blockDim.x + threadIdx.x;
    if (t >= TABN) return;

    float d = (float)t * (DMAX / (float)(TABN - 1));

    // 8 Gaussian RBFs; centers k/7, width 1/8
    float enc[8];
    #pragma unroll
    for (int k = 0; k < 8; k++) {
        float x = (d - (float)k * (1.0f / 7.0f)) * 8.0f;
        enc[k] = __expf(-x * x);
    }

    const u64* W_RAD = (const u64*)s_wrad;
    const u64* B_RAD = (const u64*)s_brad;
    const u64* W_DIR = (const u64*)s_wdir;
    const u64* W_1   = (const u64*)s_w1;
    const u64* B_1   = (const u64*)s_b1;
    const u64* W_2   = (const u64*)s_w2;
    const u64* B_2   = (const u64*)s_b2;
    const u64* W_3   = (const u64*)s_w3;
    const u64* B_3   = (const u64*)s_b3;

    u64 h2[16];
    #pragma unroll
    for (int p = 0; p < 16; p++) h2[p] = B_RAD[p];
    #pragma unroll
    for (int k = 0; k < 8; k++) {
        u64 ek2 = pack2(enc[k], enc[k]);
        #pragma unroll
        for (int p = 0; p < 16; p++) FMA2(h2[p], ek2, W_RAD[k * 16 + p], h2[p]);
    }

    u64 rad2[16];
    #pragma unroll
    for (int p = 0; p < 16; p++) rad2[p] = 0;
    u64 t1[32];
    #pragma unroll
    for (int p = 0; p < 32; p++) t1[p] = B_1[p];

    #pragma unroll
    for (int kp = 0; kp < 16; kp++) {
        float hk0, hk1;
        unpack2(h2[kp], hk0, hk1);
        u64 a0 = pack2(hk0, hk0);
        u64 a1 = pack2(hk1, hk1);
        int k0 = 2 * kp, k1 = 2 * kp + 1;
        #pragma unroll
        for (int p = 0; p < 16; p++) {
            FMA2(rad2[p], a0, W_DIR[k0 * 16 + p], rad2[p]);
            FMA2(rad2[p], a1, W_DIR[k1 * 16 + p], rad2[p]);
        }
        #pragma unroll
        for (int p = 0; p < 32; p++) {
            FMA2(t1[p], a0, W_1[k0 * 32 + p], t1[p]);
            FMA2(t1[p], a1, W_1[k1 * 32 + p], t1[p]);
        }
    }
    #pragma unroll
    for (int p = 0; p < 32; p++) {
        float lo, hi;
        unpack2(t1[p], lo, hi);
        lo = fmaxf(lo, 0.1f * lo);
        hi = fmaxf(hi, 0.1f * hi);
        t1[p] = pack2(lo, hi);
    }

    u64 t2[32];
    #pragma unroll
    for (int p = 0; p < 32; p++) t2[p] = B_2[p];
    #pragma unroll
    for (int kp = 0; kp < 32; kp++) {
        float k0v, k1v;
        unpack2(t1[kp], k0v, k1v);
        u64 a0 = pack2(k0v, k0v);
        u64 a1 = pack2(k1v, k1v);
        int k0 = 2 * kp, k1 = 2 * kp + 1;
        #pragma unroll
        for (int p = 0; p < 32; p++) {
            FMA2(t2[p], a0, W_2[k0 * 32 + p], t2[p]);
            FMA2(t2[p], a1, W_2[k1 * 32 + p], t2[p]);
        }
    }
    #pragma unroll
    for (int p = 0; p < 32; p++) {
        float lo, hi;
        unpack2(t2[p], lo, hi);
        lo = fmaxf(lo, 0.1f * lo);
        hi = fmaxf(hi, 0.1f * hi);
        t2[p] = pack2(lo, hi);
    }

    u64 one2 = pack2(1.0f, 1.0f);
    #pragma unroll
    for (int p = 0; p < 16; p++) FMA2(rad2[p], one2, B_3[p], rad2[p]);
    #pragma unroll
    for (int kp = 0; kp < 32; kp++) {
        float k0v, k1v;
        unpack2(t2[kp], k0v, k1v);
        u64 a0 = pack2(k0v, k0v);
        u64 a1 = pack2(k1v, k1v);
        int k0 = 2 * kp, k1 = 2 * kp + 1;
        #pragma unroll
        for (int p = 0; p < 16; p++) {
            FMA2(rad2[p], a0, W_3[k0 * 16 + p], rad2[p]);
            FMA2(rad2[p], a1, W_3[k1 * 16 + p], rad2[p]);
        }
    }

    // store table row (128-bit stores)
    ulonglong2* dst = (ulonglong2*)(g_table + (size_t)t * 32);
    #pragma unroll
    for (int q = 0; q < 8; q++)
        dst[q] = make_ulonglong2(rad2[2 * q], rad2[2 * q + 1]);
}

// ---------------------------------------------------------------------------
// Fused per-node kernel: gather CSR edges, look up rad = F(d) from the table
// (linear interp), accumulate moments in registers, contract with w_v / w_d.
// One warp per node; lane = channel a during gather, = output channel after.
// ---------------------------------------------------------------------------
__global__ __launch_bounds__(256)
void node_kernel(const float* __restrict__ w_v, const float* __restrict__ w_d,
                 float* __restrict__ out, int N)
{
    __shared__ float s_wv[32 * 32];
    __shared__ float s_wd[32 * 32];
    __shared__ float s_t[8][32][9];

    for (int i = threadIdx.x; i < 32 * 32; i += blockDim.x) {
        s_wv[i] = w_v[i];
        s_wd[i] = w_d[i];
    }
    __syncthreads();

    int warp = threadIdx.x >> 5;
    int lane = threadIdx.x & 31;
    int n = blockIdx.x * 8 + warp;
    if (n >= N) return;

    int beg = g_offset[n];
    int cnt = g_count[n];

    float aa = 0.f;
    float av0 = 0.f, av1 = 0.f, av2 = 0.f;
    float ad0 = 0.f, ad1 = 0.f, ad2 = 0.f, ad3 = 0.f, ad4 = 0.f, ad5 = 0.f;

    for (int t0 = 0; t0 < cnt; t0 += 32) {
        int m = cnt - t0; if (m > 32) m = 32;
        int eid = (t0 + lane < cnt) ? g_csr[beg + t0 + lane] : 0;  // coalesced
        #pragma unroll 4
        for (int i = 0; i < m; i++) {
            int e = __shfl_sync(0xffffffffu, eid, i);
            float4 rs = g_rs[e];                       // broadcast (X,Y,Z,d)
            float X = rs.x, Y = rs.y, Z = rs.z;
            // table lookup: rad[lane] = lerp(F[idx], F[idx+1])
            float u = rs.w * TSCALE;
            u = fminf(u, (float)(TABN - 1));
            int idx = (int)u;
            if (idx > TABN - 2) idx = TABN - 2;
            float frac = u - (float)idx;
            float v0 = __ldg(g_table + (size_t)idx * 32 + lane);        // coalesced
            float v1 = __ldg(g_table + (size_t)idx * 32 + 32 + lane);   // coalesced
            float ra = fmaf(frac, v1 - v0, v0);

            float tx = ra * X, ty = ra * Y, tz = ra * Z;
            aa  += ra;
            av0 += tx;  av1 += ty;  av2 += tz;
            ad0 = fmaf(tx, X, ad0);
            ad1 = fmaf(ty, Y, ad1);
            ad2 = fmaf(tz, Z, ad2);
            ad3 = fmaf(tx, Y, ad3);
            ad4 = fmaf(tx, Z, ad4);
            ad5 = fmaf(ty, Z, ad5);
        }
    }

    // A_a straight to output (lane = a)
    out[(size_t)n * 32 + lane] = aa;

    // Stage moments for cross-lane contraction
    s_t[warp][lane][0] = av0;  s_t[warp][lane][1] = av1;  s_t[warp][lane][2] = av2;
    s_t[warp][lane][3] = ad0;  s_t[warp][lane][4] = ad1;  s_t[warp][lane][5] = ad2;
    s_t[warp][lane][6] = ad3;  s_t[warp][lane][7] = ad4;  s_t[warp][lane][8] = ad5;
    __syncwarp();

    // lane = output channel
    float ov0 = 0.f, ov1 = 0.f, ov2 = 0.f;
    float od[6] = {0.f, 0.f, 0.f, 0.f, 0.f, 0.f};
    #pragma unroll
    for (int a = 0; a < 32; a++) {
        float wv = s_wv[a * 32 + lane];
        float wd = s_wd[a * 32 + lane];
        ov0 = fmaf(wv, s_t[warp][a][0], ov0);
        ov1 = fmaf(wv, s_t[warp][a][1], ov1);
        ov2 = fmaf(wv, s_t[warp][a][2], ov2);
        #pragma unroll
        for (int s = 0; s < 6; s++) od[s] = fmaf(wd, s_t[warp][a][3 + s], od[s]);
    }

    // out_v: [N][32][3] at offset N*32
    float* pv = out + (size_t)N * 32 + (size_t)n * 96 + lane * 3;
    pv[0] = ov0; pv[1] = ov1; pv[2] = ov2;

    // out_d: [N][32][3][3] at offset N*128 ; od = [XX,YY,ZZ,XY,XZ,YZ]
    float* pd = out + (size_t)N * 128 + (size_t)n * 288 + lane * 9;
    pd[0] = od[0]; pd[1] = od[3]; pd[2] = od[4];
    pd[3] = od[3]; pd[4] = od[1]; pd[5] = od[5];
    pd[6] = od[4]; pd[7] = od[5]; pd[8] = od[2];
}

// ---------------------------------------------------------------------------
// kernel_launch
// ---------------------------------------------------------------------------
extern "C" void kernel_launch(void* const* d_in, const int* in_sizes, int n_in,
                              void* d_out, int out_size) {
    const float* r_ij     = (const float*)d_in[0];
    const float* w_rad    = (const float*)d_in[1];
    const float* b_rad    = (const float*)d_in[2];
    const float* w_direct = (const float*)d_in[3];
    const float* w1       = (const float*)d_in[4];
    const float* b1       = (const float*)d_in[5];
    const float* w2       = (const float*)d_in[6];
    const float* b2       = (const float*)d_in[7];
    const float* w3       = (const float*)d_in[8];
    const float* b3       = (const float*)d_in[9];
    const float* w_v      = (const float*)d_in[10];
    const float* w_d      = (const float*)d_in[11];
    const int*   e_src    = (const int*)  d_in[12];

    int E = in_sizes[0] / 3;
    int N = out_size / 416;

    float* out = (float*)d_out;

    zero_counts_kernel<<<(N + 255) / 256, 256>>>(N);

    // Per-edge prep (d, rs) + fused degree histogram
    prep_kernel<<<(E + 255) / 256, 256>>>(r_ij, e_src, E);

    // Radial-MLP lookup table (independent of CSR; 65536 samples)
    table_kernel<<<(TABN + 127) / 128, 128>>>(
        w_rad, b_rad, w_direct, w1, b1, w2, b2, w3, b3);

    scan_kernel<<<1, 1024>>>(N);
    fill_kernel<<<(E + 255) / 256, 256>>>(e_src, E);

    // Fused gather + table interp + moments + contraction
    node_kernel<<<(N + 7) / 8, 256>>>(w_v, w_d, out, N);
}

// round 8
// speedup vs baseline: 10.5121x; 1.1431x over previous
#include <cuda_runtime.h>
#include <math.h>

#define MAX_NODES 20000
#define MAX_EDGES 640000
#define TABN      16384
#define DMAX      2.0f
// index scale: (TABN-1)/DMAX
#define TSCALE    8191.5f

// Static scratch (no allocation allowed).
__device__ float  g_table[TABN * 32];     // rad = F(d) lookup, 2MB (L2-hot)
__device__ float4 g_rs[MAX_EDGES];        // per-edge (X, Y, Z, u=table coord)
__device__ int    g_count[MAX_NODES];
__device__ int    g_offset[MAX_NODES];
__device__ int    g_cursor[MAX_NODES];
__device__ int    g_csr[MAX_EDGES];

// ---------------------------------------------------------------------------
// Packed f32x2 helpers (Blackwell FFMA2 — only reachable via PTX)
// ---------------------------------------------------------------------------
typedef unsigned long long u64;

__device__ __forceinline__ u64 pack2(float lo, float hi) {
    u64 r;
    asm("mov.b64 %0, {%1, %2};" : "=l"(r) : "f"(lo), "f"(hi));
    return r;
}
__device__ __forceinline__ void unpack2(u64 v, float& lo, float& hi) {
    asm("mov.b64 {%0, %1}, %2;" : "=f"(lo), "=f"(hi) : "l"(v));
}
#define FMA2(d, a, b, c) \
    asm("fma.rn.f32x2 %0, %1, %2, %3;" : "=l"(d) : "l"(a), "l"(b), "l"(c))

// ---------------------------------------------------------------------------
// Zero the per-node counters.
// ---------------------------------------------------------------------------
__global__ void zero_counts_kernel(int N) {
    int i = blockIdx.x * blockDim.x + threadIdx.x;
    if (i < N) g_count[i] = 0;
}

// ---------------------------------------------------------------------------
// Per-edge prep: direction + table coordinate -> g_rs; degree histogram.
// ---------------------------------------------------------------------------
__global__ void prep_kernel(const float* __restrict__ r_ij,
                            const int* __restrict__ edges_src, int E) {
    int e = blockIdx.x * blockDim.x + threadIdx.x;
    if (e >= E) return;
    atomicAdd(&g_count[edges_src[e]], 1);
    float rx = r_ij[3 * e + 0];
    float ry = r_ij[3 * e + 1];
    float rz = r_ij[3 * e + 2];
    float d2 = rx * rx + ry * ry + rz * rz;
    float d  = sqrtf(d2);
    // rs = tens_sigmoid(r * 7): r*7 / sqrt(1 + 49*d2)
    float inv = rsqrtf(1.0f + 49.0f * d2) * 7.0f;
    float u = fminf(d * TSCALE, (float)(TABN - 1));
    g_rs[e] = make_float4(rx * inv, ry * inv, rz * inv, u);
}

// ---------------------------------------------------------------------------
// Single-block exclusive scan (thread-sequential: C elems/thread, one block
// scan of 1024 partial sums).
// ---------------------------------------------------------------------------
#define SCAN_MAXC 32
__global__ void scan_kernel(int N) {
    __shared__ int s_warp[32];
    int tid = threadIdx.x;
    int lane = tid & 31;
    int wid = tid >> 5;
    int C = (N + 1023) / 1024;
    if (C > SCAN_MAXC) C = SCAN_MAXC;   // N <= 32768 supported
    int start = tid * C;

    int local[SCAN_MAXC];
    int sum = 0;
    for (int i = 0; i < C; i++) {
        int idx = start + i;
        int v = (idx < N) ? g_count[idx] : 0;
        local[i] = sum;          // exclusive within thread
        sum += v;
    }

    // block inclusive scan of per-thread sums
    int x = sum;
    #pragma unroll
    for (int off = 1; off < 32; off <<= 1) {
        int t = __shfl_up_sync(0xffffffffu, x, off);
        if (lane >= off) x += t;
    }
    if (lane == 31) s_warp[wid] = x;
    __syncthreads();
    if (wid == 0) {
        int w = s_warp[lane];
        #pragma unroll
        for (int off = 1; off < 32; off <<= 1) {
            int t = __shfl_up_sync(0xffffffffu, w, off);
            if (lane >= off) w += t;
        }
        s_warp[lane] = w;
    }
    __syncthreads();
    int base = x - sum + ((wid == 0) ? 0 : s_warp[wid - 1]);

    for (int i = 0; i < C; i++) {
        int idx = start + i;
        if (idx < N) {
            int off = base + local[i];
            g_offset[idx] = off;
            g_cursor[idx] = off;
        }
    }
}

// ---------------------------------------------------------------------------
// Fill CSR edge lists.
// ---------------------------------------------------------------------------
__global__ void fill_kernel(const int* __restrict__ edges_src, int E) {
    int e = blockIdx.x * blockDim.x + threadIdx.x;
    if (e < E) {
        int pos = atomicAdd(&g_cursor[edges_src[e]], 1);
        g_csr[pos] = e;
    }
}

// ---------------------------------------------------------------------------
// Table builder: rad = F(d) for TABN samples of d in [0, DMAX].
// Full radial MLP on packed f32x2 (one thread = one sample).
// ---------------------------------------------------------------------------
__global__ __launch_bounds__(128)
void table_kernel(const float* __restrict__ w_rad,  const float* __restrict__ b_rad,
                  const float* __restrict__ w_direct,
                  const float* __restrict__ w1, const float* __restrict__ b1,
                  const float* __restrict__ w2, const float* __restrict__ b2,
                  const float* __restrict__ w3, const float* __restrict__ b3)
{
    __shared__ __align__(16) float s_wrad[8 * 32];
    __shared__ __align__(16) float s_brad[32];
    __shared__ __align__(16) float s_wdir[32 * 32];
    __shared__ __align__(16) float s_w1[32 * 64];
    __shared__ __align__(16) float s_b1[64];
    __shared__ __align__(16) float s_w2[64 * 64];
    __shared__ __align__(16) float s_b2[64];
    __shared__ __align__(16) float s_w3[64 * 32];
    __shared__ __align__(16) float s_b3[32];

    for (int i = threadIdx.x; i < 8 * 32;  i += blockDim.x) s_wrad[i] = w_rad[i];
    for (int i = threadIdx.x; i < 32;      i += blockDim.x) s_brad[i] = b_rad[i];
    for (int i = threadIdx.x; i < 32 * 32; i += blockDim.x) s_wdir[i] = w_direct[i];
    for (int i = threadIdx.x; i < 32 * 64; i += blockDim.x) s_w1[i]   = w1[i];
    for (int i = threadIdx.x; i < 64;      i += blockDim.x) s_b1[i]   = b1[i];
    for (int i = threadIdx.x; i < 64 * 64; i += blockDim.x) s_w2[i]   = w2[i];
    for (int i = threadIdx.x; i < 64;      i += blockDim.x) s_b2[i]   = b2[i];
    for (int i = threadIdx.x; i < 64 * 32; i += blockDim.x) s_w3[i]   = w3[i];
    for (int i = threadIdx.x; i < 32;      i += blockDim.x) s_b3[i]   = b3[i];
    __syncthreads();

    int t = blockIdx.x * blockDim.x + threadIdx.x;
    if (t >= TABN) return;

    float d = (float)t * (DMAX / (float)(TABN - 1));

    // 8 Gaussian RBFs; centers k/7, width 1/8
    float enc[8];
    #pragma unroll
    for (int k = 0; k < 8; k++) {
        float x = (d - (float)k * (1.0f / 7.0f)) * 8.0f;
        enc[k] = __expf(-x * x);
    }

    const u64* W_RAD = (const u64*)s_wrad;
    const u64* B_RAD = (const u64*)s_brad;
    const u64* W_DIR = (const u64*)s_wdir;
    const u64* W_1   = (const u64*)s_w1;
    const u64* B_1   = (const u64*)s_b1;
    const u64* W_2   = (const u64*)s_w2;
    const u64* B_2   = (const u64*)s_b2;
    const u64* W_3   = (const u64*)s_w3;
    const u64* B_3   = (const u64*)s_b3;

    u64 h2[16];
    #pragma unroll
    for (int p = 0; p < 16; p++) h2[p] = B_RAD[p];
    #pragma unroll
    for (int k = 0; k < 8; k++) {
        u64 ek2 = pack2(enc[k], enc[k]);
        #pragma unroll
        for (int p = 0; p < 16; p++) FMA2(h2[p], ek2, W_RAD[k * 16 + p], h2[p]);
    }

    u64 rad2[16];
    #pragma unroll
    for (int p = 0; p < 16; p++) rad2[p] = 0;
    u64 t1[32];
    #pragma unroll
    for (int p = 0; p < 32; p++) t1[p] = B_1[p];

    #pragma unroll
    for (int kp = 0; kp < 16; kp++) {
        float hk0, hk1;
        unpack2(h2[kp], hk0, hk1);
        u64 a0 = pack2(hk0, hk0);
        u64 a1 = pack2(hk1, hk1);
        int k0 = 2 * kp, k1 = 2 * kp + 1;
        #pragma unroll
        for (int p = 0; p < 16; p++) {
            FMA2(rad2[p], a0, W_DIR[k0 * 16 + p], rad2[p]);
            FMA2(rad2[p], a1, W_DIR[k1 * 16 + p], rad2[p]);
        }
        #pragma unroll
        for (int p = 0; p < 32; p++) {
            FMA2(t1[p], a0, W_1[k0 * 32 + p], t1[p]);
            FMA2(t1[p], a1, W_1[k1 * 32 + p], t1[p]);
        }
    }
    #pragma unroll
    for (int p = 0; p < 32; p++) {
        float lo, hi;
        unpack2(t1[p], lo, hi);
        lo = fmaxf(lo, 0.1f * lo);
        hi = fmaxf(hi, 0.1f * hi);
        t1[p] = pack2(lo, hi);
    }

    u64 t2[32];
    #pragma unroll
    for (int p = 0; p < 32; p++) t2[p] = B_2[p];
    #pragma unroll
    for (int kp = 0; kp < 32; kp++) {
        float k0v, k1v;
        unpack2(t1[kp], k0v, k1v);
        u64 a0 = pack2(k0v, k0v);
        u64 a1 = pack2(k1v, k1v);
        int k0 = 2 * kp, k1 = 2 * kp + 1;
        #pragma unroll
        for (int p = 0; p < 32; p++) {
            FMA2(t2[p], a0, W_2[k0 * 32 + p], t2[p]);
            FMA2(t2[p], a1, W_2[k1 * 32 + p], t2[p]);
        }
    }
    #pragma unroll
    for (int p = 0; p < 32; p++) {
        float lo, hi;
        unpack2(t2[p], lo, hi);
        lo = fmaxf(lo, 0.1f * lo);
        hi = fmaxf(hi, 0.1f * hi);
        t2[p] = pack2(lo, hi);
    }

    u64 one2 = pack2(1.0f, 1.0f);
    #pragma unroll
    for (int p = 0; p < 16; p++) FMA2(rad2[p], one2, B_3[p], rad2[p]);
    #pragma unroll
    for (int kp = 0; kp < 32; kp++) {
        float k0v, k1v;
        unpack2(t2[kp], k0v, k1v);
        u64 a0 = pack2(k0v, k0v);
        u64 a1 = pack2(k1v, k1v);
        int k0 = 2 * kp, k1 = 2 * kp + 1;
        #pragma unroll
        for (int p = 0; p < 16; p++) {
            FMA2(rad2[p], a0, W_3[k0 * 16 + p], rad2[p]);
            FMA2(rad2[p], a1, W_3[k1 * 16 + p], rad2[p]);
        }
    }

    // store table row (128-bit stores)
    ulonglong2* dst = (ulonglong2*)(g_table + (size_t)t * 32);
    #pragma unroll
    for (int q = 0; q < 8; q++)
        dst[q] = make_ulonglong2(rad2[2 * q], rad2[2 * q + 1]);
}

// ---------------------------------------------------------------------------
// Fused per-node kernel. One warp per node; the warp is split into 4 edge
// groups x 8 channel lanes: per step, 4 edges are processed with float4
// table loads (4x the memory parallelism of the channel-per-lane layout).
// acc[c][m]: c = channel quarter (lane&7)*4+c, m = [aa, av*3, ad*6].
// ---------------------------------------------------------------------------
__global__ __launch_bounds__(256)
void node_kernel(const float* __restrict__ w_v, const float* __restrict__ w_d,
                 float* __restrict__ out, int N)
{
    __shared__ float s_wv[32 * 32];
    __shared__ float s_wd[32 * 32];
    __shared__ float s_t[8][32][9];

    for (int i = threadIdx.x; i < 32 * 32; i += blockDim.x) {
        s_wv[i] = w_v[i];
        s_wd[i] = w_d[i];
    }
    __syncthreads();

    int warp = threadIdx.x >> 5;
    int lane = threadIdx.x & 31;
    int g = lane >> 3;      // edge group 0..3
    int l = lane & 7;       // channel quarter 0..7 (channels l*4..l*4+3)
    int n = blockIdx.x * 8 + warp;
    if (n >= N) return;

    int beg = g_offset[n];
    int cnt = g_count[n];

    float acc[4][10];
    #pragma unroll
    for (int c = 0; c < 4; c++)
        #pragma unroll
        for (int m = 0; m < 10; m++) acc[c][m] = 0.0f;

    for (int t0 = 0; t0 < cnt; t0 += 32) {
        int eid = (t0 + lane < cnt) ? g_csr[beg + t0 + lane] : 0;  // coalesced
        int rem = cnt - t0; if (rem > 32) rem = 32;
        int steps = (rem + 3) >> 2;
        #pragma unroll 2
        for (int i = 0; i < steps; i++) {
            int j = i * 4 + g;
            int e = __shfl_sync(0xffffffffu, eid, j);
            float wgt = (t0 + j < cnt) ? 1.0f : 0.0f;
            float4 rs = __ldg(&g_rs[e]);          // 4 distinct addrs / warp
            float u = rs.w;
            int idx = (int)u;
            if (idx > TABN - 2) idx = TABN - 2;
            float frac = u - (float)idx;
            const float4* rp = (const float4*)(g_table + (size_t)idx * 32) + l;
            float4 v0 = __ldg(rp);                // 4 x 128B rows / warp
            float4 v1 = __ldg(rp + 8);
            float X = rs.x, Y = rs.y, Z = rs.z;

            float ra[4];
            ra[0] = fmaf(frac, v1.x - v0.x, v0.x) * wgt;
            ra[1] = fmaf(frac, v1.y - v0.y, v0.y) * wgt;
            ra[2] = fmaf(frac, v1.z - v0.z, v0.z) * wgt;
            ra[3] = fmaf(frac, v1.w - v0.w, v0.w) * wgt;

            #pragma unroll
            for (int c = 0; c < 4; c++) {
                float r = ra[c];
                float tx = r * X, ty = r * Y, tz = r * Z;
                acc[c][0] += r;
                acc[c][1] += tx;  acc[c][2] += ty;  acc[c][3] += tz;
                acc[c][4] = fmaf(tx, X, acc[c][4]);   // XX
                acc[c][5] = fmaf(ty, Y, acc[c][5]);   // YY
                acc[c][6] = fmaf(tz, Z, acc[c][6]);   // ZZ
                acc[c][7] = fmaf(tx, Y, acc[c][7]);   // XY
                acc[c][8] = fmaf(tx, Z, acc[c][8]);   // XZ
                acc[c][9] = fmaf(ty, Z, acc[c][9]);   // YZ
            }
        }
    }

    // reduce across the 4 edge groups
    #pragma unroll
    for (int c = 0; c < 4; c++)
        #pragma unroll
        for (int m = 0; m < 10; m++) {
            acc[c][m] += __shfl_xor_sync(0xffffffffu, acc[c][m], 8);
            acc[c][m] += __shfl_xor_sync(0xffffffffu, acc[c][m], 16);
        }

    if (g == 0) {
        // A_a: channels l*4..l*4+3, contiguous float4 store
        float4 aav = make_float4(acc[0][0], acc[1][0], acc[2][0], acc[3][0]);
        *(float4*)(out + (size_t)n * 32 + l * 4) = aav;
        #pragma unroll
        for (int c = 0; c < 4; c++)
            #pragma unroll
            for (int m = 0; m < 9; m++)
                s_t[warp][l * 4 + c][m] = acc[c][m + 1];
    }
    __syncwarp();

    // lane = output channel
    float ov0 = 0.f, ov1 = 0.f, ov2 = 0.f;
    float od[6] = {0.f, 0.f, 0.f, 0.f, 0.f, 0.f};
    #pragma unroll
    for (int a = 0; a < 32; a++) {
        float wv = s_wv[a * 32 + lane];
        float wd = s_wd[a * 32 + lane];
        ov0 = fmaf(wv, s_t[warp][a][0], ov0);
        ov1 = fmaf(wv, s_t[warp][a][1], ov1);
        ov2 = fmaf(wv, s_t[warp][a][2], ov2);
        #pragma unroll
        for (int s = 0; s < 6; s++) od[s] = fmaf(wd, s_t[warp][a][3 + s], od[s]);
    }

    // out_v: [N][32][3] at offset N*32
    float* pv = out + (size_t)N * 32 + (size_t)n * 96 + lane * 3;
    pv[0] = ov0; pv[1] = ov1; pv[2] = ov2;

    // out_d: [N][32][3][3] at offset N*128 ; od = [XX,YY,ZZ,XY,XZ,YZ]
    float* pd = out + (size_t)N * 128 + (size_t)n * 288 + lane * 9;
    pd[0] = od[0]; pd[1] = od[3]; pd[2] = od[4];
    pd[3] = od[3]; pd[4] = od[1]; pd[5] = od[5];
    pd[6] = od[4]; pd[7] = od[5]; pd[8] = od[2];
}

// ---------------------------------------------------------------------------
// kernel_launch
// ---------------------------------------------------------------------------
extern "C" void kernel_launch(void* const* d_in, const int* in_sizes, int n_in,
                              void* d_out, int out_size) {
    const float* r_ij     = (const float*)d_in[0];
    const float* w_rad    = (const float*)d_in[1];
    const float* b_rad    = (const float*)d_in[2];
    const float* w_direct = (const float*)d_in[3];
    const float* w1       = (const float*)d_in[4];
    const float* b1       = (const float*)d_in[5];
    const float* w2       = (const float*)d_in[6];
    const float* b2       = (const float*)d_in[7];
    const float* w3       = (const float*)d_in[8];
    const float* b3       = (const float*)d_in[9];
    const float* w_v      = (const float*)d_in[10];
    const float* w_d      = (const float*)d_in[11];
    const int*   e_src    = (const int*)  d_in[12];

    int E = in_sizes[0] / 3;
    int N = out_size / 416;

    float* out = (float*)d_out;

    zero_counts_kernel<<<(N + 255) / 256, 256>>>(N);

    // Per-edge prep (rs, table coord) + fused degree histogram
    prep_kernel<<<(E + 255) / 256, 256>>>(r_ij, e_src, E);

    // Radial-MLP lookup table (16384 samples)
    table_kernel<<<(TABN + 127) / 128, 128>>>(
        w_rad, b_rad, w_direct, w1, b1, w2, b2, w3, b3);

    scan_kernel<<<1, 1024>>>(N);
    fill_kernel<<<(E + 255) / 256, 256>>>(e_src, E);

    // Fused gather + table interp + moments + contraction
    node_kernel<<<(N + 7) / 8, 256>>>(w_v, w_d, out, N);
}

// round 9
// speedup vs baseline: 14.6408x; 1.3928x over previous
#include <cuda_runtime.h>
#include <math.h>

#define MAX_NODES 20000
#define MAX_EDGES 640000
#define SLOTS     160          // padded per-node edge-list capacity (max degree ~66)
#define TABN      16384
#define DMAX      2.0f
#define TSCALE    8191.5f      // (TABN-1)/DMAX

// Static scratch (no allocation allowed).
__device__ float  g_table[TABN * 32];       // rad = F(d) lookup, 2MB (L2-hot)
__device__ float4 g_rs[MAX_EDGES];          // per-edge (X, Y, Z, u=table coord)
__device__ int    g_count[MAX_NODES];
__device__ int    g_slots[MAX_NODES * SLOTS];  // padded per-node edge IDs

// ---------------------------------------------------------------------------
// Packed f32x2 helpers (Blackwell FFMA2 — only reachable via PTX)
// ---------------------------------------------------------------------------
typedef unsigned long long u64;

__device__ __forceinline__ u64 pack2(float lo, float hi) {
    u64 r;
    asm("mov.b64 %0, {%1, %2};" : "=l"(r) : "f"(lo), "f"(hi));
    return r;
}
__device__ __forceinline__ void unpack2(u64 v, float& lo, float& hi) {
    asm("mov.b64 {%0, %1}, %2;" : "=f"(lo), "=f"(hi) : "l"(v));
}
#define FMA2(d, a, b, c) \
    asm("fma.rn.f32x2 %0, %1, %2, %3;" : "=l"(d) : "l"(a), "l"(b), "l"(c))

// ---------------------------------------------------------------------------
// Zero the per-node counters.
// ---------------------------------------------------------------------------
__global__ void zero_counts_kernel(int N) {
    int i = blockIdx.x * blockDim.x + threadIdx.x;
    if (i < N) g_count[i] = 0;
}

// ---------------------------------------------------------------------------
// Per-edge prep: direction + table coordinate -> g_rs; padded bucket insert
// (replaces histogram + scan + fill: no CSR, no prefix sum).
// ---------------------------------------------------------------------------
__global__ void prep_kernel(const float* __restrict__ r_ij,
                            const int* __restrict__ edges_src, int E) {
    int e = blockIdx.x * blockDim.x + threadIdx.x;
    if (e >= E) return;

    int n = edges_src[e];
    int slot = atomicAdd(&g_count[n], 1);
    if (slot < SLOTS) g_slots[n * SLOTS + slot] = e;

    float rx = r_ij[3 * e + 0];
    float ry = r_ij[3 * e + 1];
    float rz = r_ij[3 * e + 2];
    float d2 = rx * rx + ry * ry + rz * rz;
    float d  = sqrtf(d2);
    // rs = tens_sigmoid(r * 7): r*7 / sqrt(1 + 49*d2)
    float inv = rsqrtf(1.0f + 49.0f * d2) * 7.0f;
    float u = fminf(d * TSCALE, (float)(TABN - 1));
    g_rs[e] = make_float4(rx * inv, ry * inv, rz * inv, u);
}

// ---------------------------------------------------------------------------
// Table builder: rad = F(d) for TABN samples of d in [0, DMAX].
// Full radial MLP on packed f32x2 (one thread = one sample).
// ---------------------------------------------------------------------------
__global__ __launch_bounds__(128)
void table_kernel(const float* __restrict__ w_rad,  const float* __restrict__ b_rad,
                  const float* __restrict__ w_direct,
                  const float* __restrict__ w1, const float* __restrict__ b1,
                  const float* __restrict__ w2, const float* __restrict__ b2,
                  const float* __restrict__ w3, const float* __restrict__ b3)
{
    __shared__ __align__(16) float s_wrad[8 * 32];
    __shared__ __align__(16) float s_brad[32];
    __shared__ __align__(16) float s_wdir[32 * 32];
    __shared__ __align__(16) float s_w1[32 * 64];
    __shared__ __align__(16) float s_b1[64];
    __shared__ __align__(16) float s_w2[64 * 64];
    __shared__ __align__(16) float s_b2[64];
    __shared__ __align__(16) float s_w3[64 * 32];
    __shared__ __align__(16) float s_b3[32];

    for (int i = threadIdx.x; i < 8 * 32;  i += blockDim.x) s_wrad[i] = w_rad[i];
    for (int i = threadIdx.x; i < 32;      i += blockDim.x) s_brad[i] = b_rad[i];
    for (int i = threadIdx.x; i < 32 * 32; i += blockDim.x) s_wdir[i] = w_direct[i];
    for (int i = threadIdx.x; i < 32 * 64; i += blockDim.x) s_w1[i]   = w1[i];
    for (int i = threadIdx.x; i < 64;      i += blockDim.x) s_b1[i]   = b1[i];
    for (int i = threadIdx.x; i < 64 * 64; i += blockDim.x) s_w2[i]   = w2[i];
    for (int i = threadIdx.x; i < 64;      i += blockDim.x) s_b2[i]   = b2[i];
    for (int i = threadIdx.x; i < 64 * 32; i += blockDim.x) s_w3[i]   = w3[i];
    for (int i = threadIdx.x; i < 32;      i += blockDim.x) s_b3[i]   = b3[i];
    __syncthreads();

    int t = blockIdx.x * blockDim.x + threadIdx.x;
    if (t >= TABN) return;

    float d = (float)t * (DMAX / (float)(TABN - 1));

    // 8 Gaussian RBFs; centers k/7, width 1/8
    float enc[8];
    #pragma unroll
    for (int k = 0; k < 8; k++) {
        float x = (d - (float)k * (1.0f / 7.0f)) * 8.0f;
        enc[k] = __expf(-x * x);
    }

    const u64* W_RAD = (const u64*)s_wrad;
    const u64* B_RAD = (const u64*)s_brad;
    const u64* W_DIR = (const u64*)s_wdir;
    const u64* W_1   = (const u64*)s_w1;
    const u64* B_1   = (const u64*)s_b1;
    const u64* W_2   = (const u64*)s_w2;
    const u64* B_2   = (const u64*)s_b2;
    const u64* W_3   = (const u64*)s_w3;
    const u64* B_3   = (const u64*)s_b3;

    u64 h2[16];
    #pragma unroll
    for (int p = 0; p < 16; p++) h2[p] = B_RAD[p];
    #pragma unroll
    for (int k = 0; k < 8; k++) {
        u64 ek2 = pack2(enc[k], enc[k]);
        #pragma unroll
        for (int p = 0; p < 16; p++) FMA2(h2[p], ek2, W_RAD[k * 16 + p], h2[p]);
    }

    u64 rad2[16];
    #pragma unroll
    for (int p = 0; p < 16; p++) rad2[p] = 0;
    u64 t1[32];
    #pragma unroll
    for (int p = 0; p < 32; p++) t1[p] = B_1[p];

    #pragma unroll
    for (int kp = 0; kp < 16; kp++) {
        float hk0, hk1;
        unpack2(h2[kp], hk0, hk1);
        u64 a0 = pack2(hk0, hk0);
        u64 a1 = pack2(hk1, hk1);
        int k0 = 2 * kp, k1 = 2 * kp + 1;
        #pragma unroll
        for (int p = 0; p < 16; p++) {
            FMA2(rad2[p], a0, W_DIR[k0 * 16 + p], rad2[p]);
            FMA2(rad2[p], a1, W_DIR[k1 * 16 + p], rad2[p]);
        }
        #pragma unroll
        for (int p = 0; p < 32; p++) {
            FMA2(t1[p], a0, W_1[k0 * 32 + p], t1[p]);
            FMA2(t1[p], a1, W_1[k1 * 32 + p], t1[p]);
        }
    }
    #pragma unroll
    for (int p = 0; p < 32; p++) {
        float lo, hi;
        unpack2(t1[p], lo, hi);
        lo = fmaxf(lo, 0.1f * lo);
        hi = fmaxf(hi, 0.1f * hi);
        t1[p] = pack2(lo, hi);
    }

    u64 t2[32];
    #pragma unroll
    for (int p = 0; p < 32; p++) t2[p] = B_2[p];
    #pragma unroll
    for (int kp = 0; kp < 32; kp++) {
        float k0v, k1v;
        unpack2(t1[kp], k0v, k1v);
        u64 a0 = pack2(k0v, k0v);
        u64 a1 = pack2(k1v, k1v);
        int k0 = 2 * kp, k1 = 2 * kp + 1;
        #pragma unroll
        for (int p = 0; p < 32; p++) {
            FMA2(t2[p], a0, W_2[k0 * 32 + p], t2[p]);
            FMA2(t2[p], a1, W_2[k1 * 32 + p], t2[p]);
        }
    }
    #pragma unroll
    for (int p = 0; p < 32; p++) {
        float lo, hi;
        unpack2(t2[p], lo, hi);
        lo = fmaxf(lo, 0.1f * lo);
        hi = fmaxf(hi, 0.1f * hi);
        t2[p] = pack2(lo, hi);
    }

    u64 one2 = pack2(1.0f, 1.0f);
    #pragma unroll
    for (int p = 0; p < 16; p++) FMA2(rad2[p], one2, B_3[p], rad2[p]);
    #pragma unroll
    for (int kp = 0; kp < 32; kp++) {
        float k0v, k1v;
        unpack2(t2[kp], k0v, k1v);
        u64 a0 = pack2(k0v, k0v);
        u64 a1 = pack2(k1v, k1v);
        int k0 = 2 * kp, k1 = 2 * kp + 1;
        #pragma unroll
        for (int p = 0; p < 16; p++) {
            FMA2(rad2[p], a0, W_3[k0 * 16 + p], rad2[p]);
            FMA2(rad2[p], a1, W_3[k1 * 16 + p], rad2[p]);
        }
    }

    // store table row (128-bit stores)
    ulonglong2* dst = (ulonglong2*)(g_table + (size_t)t * 32);
    #pragma unroll
    for (int q = 0; q < 8; q++)
        dst[q] = make_ulonglong2(rad2[2 * q], rad2[2 * q + 1]);
}

// ---------------------------------------------------------------------------
// Fused per-node kernel. One warp per node; warp split into 4 edge groups x
// 8 channel lanes; per step 4 edges are processed with float4 table loads.
// acc[c][m]: c = channel quarter (lane&7)*4+c, m = [aa, av*3, ad*6].
// ---------------------------------------------------------------------------
__global__ __launch_bounds__(256)
void node_kernel(const float* __restrict__ w_v, const float* __restrict__ w_d,
                 float* __restrict__ out, int N)
{
    __shared__ float s_wv[32 * 32];
    __shared__ float s_wd[32 * 32];
    __shared__ float s_t[8][32][9];

    for (int i = threadIdx.x; i < 32 * 32; i += blockDim.x) {
        s_wv[i] = w_v[i];
        s_wd[i] = w_d[i];
    }
    __syncthreads();

    int warp = threadIdx.x >> 5;
    int lane = threadIdx.x & 31;
    int g = lane >> 3;      // edge group 0..3
    int l = lane & 7;       // channel quarter 0..7 (channels l*4..l*4+3)
    int n = blockIdx.x * 8 + warp;
    if (n >= N) return;

    const int* slots = g_slots + n * SLOTS;
    int cnt = g_count[n];
    if (cnt > SLOTS) cnt = SLOTS;

    float acc[4][10];
    #pragma unroll
    for (int c = 0; c < 4; c++)
        #pragma unroll
        for (int m = 0; m < 10; m++) acc[c][m] = 0.0f;

    for (int t0 = 0; t0 < cnt; t0 += 32) {
        int eid = (t0 + lane < cnt) ? slots[t0 + lane] : 0;   // coalesced
        int rem = cnt - t0; if (rem > 32) rem = 32;
        int steps = (rem + 3) >> 2;
        #pragma unroll 2
        for (int i = 0; i < steps; i++) {
            int j = i * 4 + g;
            int e = __shfl_sync(0xffffffffu, eid, j);
            float wgt = (t0 + j < cnt) ? 1.0f : 0.0f;
            float4 rs = __ldg(&g_rs[e]);          // 4 distinct addrs / warp
            float u = rs.w;
            int idx = (int)u;
            if (idx > TABN - 2) idx = TABN - 2;
            float frac = u - (float)idx;
            const float4* rp = (const float4*)(g_table + (size_t)idx * 32) + l;
            float4 v0 = __ldg(rp);                // 4 x 128B rows / warp
            float4 v1 = __ldg(rp + 8);
            float X = rs.x, Y = rs.y, Z = rs.z;

            float ra[4];
            ra[0] = fmaf(frac, v1.x - v0.x, v0.x) * wgt;
            ra[1] = fmaf(frac, v1.y - v0.y, v0.y) * wgt;
            ra[2] = fmaf(frac, v1.z - v0.z, v0.z) * wgt;
            ra[3] = fmaf(frac, v1.w - v0.w, v0.w) * wgt;

            #pragma unroll
            for (int c = 0; c < 4; c++) {
                float r = ra[c];
                float tx = r * X, ty = r * Y, tz = r * Z;
                acc[c][0] += r;
                acc[c][1] += tx;  acc[c][2] += ty;  acc[c][3] += tz;
                acc[c][4] = fmaf(tx, X, acc[c][4]);   // XX
                acc[c][5] = fmaf(ty, Y, acc[c][5]);   // YY
                acc[c][6] = fmaf(tz, Z, acc[c][6]);   // ZZ
                acc[c][7] = fmaf(tx, Y, acc[c][7]);   // XY
                acc[c][8] = fmaf(tx, Z, acc[c][8]);   // XZ
                acc[c][9] = fmaf(ty, Z, acc[c][9]);   // YZ
            }
        }
    }

    // reduce across the 4 edge groups
    #pragma unroll
    for (int c = 0; c < 4; c++)
        #pragma unroll
        for (int m = 0; m < 10; m++) {
            acc[c][m] += __shfl_xor_sync(0xffffffffu, acc[c][m], 8);
            acc[c][m] += __shfl_xor_sync(0xffffffffu, acc[c][m], 16);
        }

    if (g == 0) {
        // A_a: channels l*4..l*4+3, contiguous float4 store
        float4 aav = make_float4(acc[0][0], acc[1][0], acc[2][0], acc[3][0]);
        *(float4*)(out + (size_t)n * 32 + l * 4) = aav;
        #pragma unroll
        for (int c = 0; c < 4; c++)
            #pragma unroll
            for (int m = 0; m < 9; m++)
                s_t[warp][l * 4 + c][m] = acc[c][m + 1];
    }
    __syncwarp();

    // lane = output channel
    float ov0 = 0.f, ov1 = 0.f, ov2 = 0.f;
    float od[6] = {0.f, 0.f, 0.f, 0.f, 0.f, 0.f};
    #pragma unroll
    for (int a = 0; a < 32; a++) {
        float wv = s_wv[a * 32 + lane];
        float wd = s_wd[a * 32 + lane];
        ov0 = fmaf(wv, s_t[warp][a][0], ov0);
        ov1 = fmaf(wv, s_t[warp][a][1], ov1);
        ov2 = fmaf(wv, s_t[warp][a][2], ov2);
        #pragma unroll
        for (int s = 0; s < 6; s++) od[s] = fmaf(wd, s_t[warp][a][3 + s], od[s]);
    }

    // out_v: [N][32][3] at offset N*32
    float* pv = out + (size_t)N * 32 + (size_t)n * 96 + lane * 3;
    pv[0] = ov0; pv[1] = ov1; pv[2] = ov2;

    // out_d: [N][32][3][3] at offset N*128 ; od = [XX,YY,ZZ,XY,XZ,YZ]
    float* pd = out + (size_t)N * 128 + (size_t)n * 288 + lane * 9;
    pd[0] = od[0]; pd[1] = od[3]; pd[2] = od[4];
    pd[3] = od[3]; pd[4] = od[1]; pd[5] = od[5];
    pd[6] = od[4]; pd[7] = od[5]; pd[8] = od[2];
}

// ---------------------------------------------------------------------------
// kernel_launch
// ---------------------------------------------------------------------------
extern "C" void kernel_launch(void* const* d_in, const int* in_sizes, int n_in,
                              void* d_out, int out_size) {
    const float* r_ij     = (const float*)d_in[0];
    const float* w_rad    = (const float*)d_in[1];
    const float* b_rad    = (const float*)d_in[2];
    const float* w_direct = (const float*)d_in[3];
    const float* w1       = (const float*)d_in[4];
    const float* b1       = (const float*)d_in[5];
    const float* w2       = (const float*)d_in[6];
    const float* b2       = (const float*)d_in[7];
    const float* w3       = (const float*)d_in[8];
    const float* b3       = (const float*)d_in[9];
    const float* w_v      = (const float*)d_in[10];
    const float* w_d      = (const float*)d_in[11];
    const int*   e_src    = (const int*)  d_in[12];

    int E = in_sizes[0] / 3;
    int N = out_size / 416;

    float* out = (float*)d_out;

    zero_counts_kernel<<<(N + 255) / 256, 256>>>(N);

    // Per-edge prep (rs, table coord) + padded bucket insert (no CSR build)
    prep_kernel<<<(E + 255) / 256, 256>>>(r_ij, e_src, E);

    // Radial-MLP lookup table (16384 samples) — independent of prep
    table_kernel<<<(TABN + 127) / 128, 128>>>(
        w_rad, b_rad, w_direct, w1, b1, w2, b2, w3, b3);

    // Fused gather + table interp + moments + contraction
    node_kernel<<<(N + 7) / 8, 256>>>(w_v, w_d, out, N);
}

// round 11
// speedup vs baseline: 15.7882x; 1.0784x over previous
#include <cuda_runtime.h>
#include <math.h>

#define MAX_NODES 20000
#define MAX_EDGES 640000
#define SLOTS     160          // padded per-node edge capacity (max degree ~66)
#define TABN      16384
#define DMAX      2.0f
#define TSCALE    8191.5f      // (TABN-1)/DMAX

// Static scratch (no allocation allowed).
__device__ float  g_table[TABN * 32];              // rad = F(d) lookup, 2MB (L2-hot)
__device__ int    g_count[MAX_NODES];
__device__ float4 g_slot_rs[MAX_NODES * SLOTS];    // per-slot payload (X,Y,Z,u)

// ---------------------------------------------------------------------------
// Packed f32x2 helpers (Blackwell FFMA2 — only reachable via PTX)
// ---------------------------------------------------------------------------
typedef unsigned long long u64;

__device__ __forceinline__ u64 pack2(float lo, float hi) {
    u64 r;
    asm("mov.b64 %0, {%1, %2};" : "=l"(r) : "f"(lo), "f"(hi));
    return r;
}
__device__ __forceinline__ void unpack2(u64 v, float& lo, float& hi) {
    asm("mov.b64 {%0, %1}, %2;" : "=f"(lo), "=f"(hi) : "l"(v));
}
#define FMA2(d, a, b, c) \
    asm("fma.rn.f32x2 %0, %1, %2, %3;" : "=l"(d) : "l"(a), "l"(b), "l"(c))

// ---------------------------------------------------------------------------
// Zero the per-node counters.
// ---------------------------------------------------------------------------
__global__ void zero_counts_kernel(int N) {
    int i = blockIdx.x * blockDim.x + threadIdx.x;
    if (i < N) g_count[i] = 0;
}

// ---------------------------------------------------------------------------
// Per-edge prep: compute (X,Y,Z,u) and write it DIRECTLY into the node's
// slot list (payload-in-slot: node kernel never needs the edge id).
// ---------------------------------------------------------------------------
__global__ void prep_kernel(const float* __restrict__ r_ij,
                            const int* __restrict__ edges_src, int E) {
    int e = blockIdx.x * blockDim.x + threadIdx.x;
    if (e >= E) return;

    int n = edges_src[e];
    int slot = atomicAdd(&g_count[n], 1);

    float rx = r_ij[3 * e + 0];
    float ry = r_ij[3 * e + 1];
    float rz = r_ij[3 * e + 2];
    float d2 = rx * rx + ry * ry + rz * rz;
    float d  = sqrtf(d2);
    // rs = tens_sigmoid(r * 7): r*7 / sqrt(1 + 49*d2)
    float inv = rsqrtf(1.0f + 49.0f * d2) * 7.0f;
    float u = fminf(d * TSCALE, (float)(TABN - 1));
    if (slot < SLOTS)
        g_slot_rs[n * SLOTS + slot] = make_float4(rx * inv, ry * inv, rz * inv, u);
}

// ---------------------------------------------------------------------------
// Table builder: rad = F(d) for TABN samples of d in [0, DMAX].
// Full radial MLP on packed f32x2 (one thread = one sample).
// ---------------------------------------------------------------------------
__global__ __launch_bounds__(128)
void table_kernel(const float* __restrict__ w_rad,  const float* __restrict__ b_rad,
                  const float* __restrict__ w_direct,
                  const float* __restrict__ w1, const float* __restrict__ b1,
                  const float* __restrict__ w2, const float* __restrict__ b2,
                  const float* __restrict__ w3, const float* __restrict__ b3)
{
    __shared__ __align__(16) float s_wrad[8 * 32];
    __shared__ __align__(16) float s_brad[32];
    __shared__ __align__(16) float s_wdir[32 * 32];
    __shared__ __align__(16) float s_w1[32 * 64];
    __shared__ __align__(16) float s_b1[64];
    __shared__ __align__(16) float s_w2[64 * 64];
    __shared__ __align__(16) float s_b2[64];
    __shared__ __align__(16) float s_w3[64 * 32];
    __shared__ __align__(16) float s_b3[32];

    for (int i = threadIdx.x; i < 8 * 32;  i += blockDim.x) s_wrad[i] = w_rad[i];
    for (int i = threadIdx.x; i < 32;      i += blockDim.x) s_brad[i] = b_rad[i];
    for (int i = threadIdx.x; i < 32 * 32; i += blockDim.x) s_wdir[i] = w_direct[i];
    for (int i = threadIdx.x; i < 32 * 64; i += blockDim.x) s_w1[i]   = w1[i];
    for (int i = threadIdx.x; i < 64;      i += blockDim.x) s_b1[i]   = b1[i];
    for (int i = threadIdx.x; i < 64 * 64; i += blockDim.x) s_w2[i]   = w2[i];
    for (int i = threadIdx.x; i < 64;      i += blockDim.x) s_b2[i]   = b2[i];
    for (int i = threadIdx.x; i < 64 * 32; i += blockDim.x) s_w3[i]   = w3[i];
    for (int i = threadIdx.x; i < 32;      i += blockDim.x) s_b3[i]   = b3[i];
    __syncthreads();

    int t = blockIdx.x * blockDim.x + threadIdx.x;
    if (t >= TABN) return;

    float d = (float)t * (DMAX / (float)(TABN - 1));

    // 8 Gaussian RBFs; centers k/7, width 1/8
    float enc[8];
    #pragma unroll
    for (int k = 0; k < 8; k++) {
        float x = (d - (float)k * (1.0f / 7.0f)) * 8.0f;
        enc[k] = __expf(-x * x);
    }

    const u64* W_RAD = (const u64*)s_wrad;
    const u64* B_RAD = (const u64*)s_brad;
    const u64* W_DIR = (const u64*)s_wdir;
    const u64* W_1   = (const u64*)s_w1;
    const u64* B_1   = (const u64*)s_b1;
    const u64* W_2   = (const u64*)s_w2;
    const u64* B_2   = (const u64*)s_b2;
    const u64* W_3   = (const u64*)s_w3;
    const u64* B_3   = (const u64*)s_b3;

    u64 h2[16];
    #pragma unroll
    for (int p = 0; p < 16; p++) h2[p] = B_RAD[p];
    #pragma unroll
    for (int k = 0; k < 8; k++) {
        u64 ek2 = pack2(enc[k], enc[k]);
        #pragma unroll
        for (int p = 0; p < 16; p++) FMA2(h2[p], ek2, W_RAD[k * 16 + p], h2[p]);
    }

    u64 rad2[16];
    #pragma unroll
    for (int p = 0; p < 16; p++) rad2[p] = 0;
    u64 t1[32];
    #pragma unroll
    for (int p = 0; p < 32; p++) t1[p] = B_1[p];

    #pragma unroll
    for (int kp = 0; kp < 16; kp++) {
        float hk0, hk1;
        unpack2(h2[kp], hk0, hk1);
        u64 a0 = pack2(hk0, hk0);
        u64 a1 = pack2(hk1, hk1);
        int k0 = 2 * kp, k1 = 2 * kp + 1;
        #pragma unroll
        for (int p = 0; p < 16; p++) {
            FMA2(rad2[p], a0, W_DIR[k0 * 16 + p], rad2[p]);
            FMA2(rad2[p], a1, W_DIR[k1 * 16 + p], rad2[p]);
        }
        #pragma unroll
        for (int p = 0; p < 32; p++) {
            FMA2(t1[p], a0, W_1[k0 * 32 + p], t1[p]);
            FMA2(t1[p], a1, W_1[k1 * 32 + p], t1[p]);
        }
    }
    #pragma unroll
    for (int p = 0; p < 32; p++) {
        float lo, hi;
        unpack2(t1[p], lo, hi);
        lo = fmaxf(lo, 0.1f * lo);
        hi = fmaxf(hi, 0.1f * hi);
        t1[p] = pack2(lo, hi);
    }

    u64 t2[32];
    #pragma unroll
    for (int p = 0; p < 32; p++) t2[p] = B_2[p];
    #pragma unroll
    for (int kp = 0; kp < 32; kp++) {
        float k0v, k1v;
        unpack2(t1[kp], k0v, k1v);
        u64 a0 = pack2(k0v, k0v);
        u64 a1 = pack2(k1v, k1v);
        int k0 = 2 * kp, k1 = 2 * kp + 1;
        #pragma unroll
        for (int p = 0; p < 32; p++) {
            FMA2(t2[p], a0, W_2[k0 * 32 + p], t2[p]);
            FMA2(t2[p], a1, W_2[k1 * 32 + p], t2[p]);
        }
    }
    #pragma unroll
    for (int p = 0; p < 32; p++) {
        float lo, hi;
        unpack2(t2[p], lo, hi);
        lo = fmaxf(lo, 0.1f * lo);
        hi = fmaxf(hi, 0.1f * hi);
        t2[p] = pack2(lo, hi);
    }

    u64 one2 = pack2(1.0f, 1.0f);
    #pragma unroll
    for (int p = 0; p < 16; p++) FMA2(rad2[p], one2, B_3[p], rad2[p]);
    #pragma unroll
    for (int kp = 0; kp < 32; kp++) {
        float k0v, k1v;
        unpack2(t2[kp], k0v, k1v);
        u64 a0 = pack2(k0v, k0v);
        u64 a1 = pack2(k1v, k1v);
        int k0 = 2 * kp, k1 = 2 * kp + 1;
        #pragma unroll
        for (int p = 0; p < 16; p++) {
            FMA2(rad2[p], a0, W_3[k0 * 16 + p], rad2[p]);
            FMA2(rad2[p], a1, W_3[k1 * 16 + p], rad2[p]);
        }
    }

    // store table row (128-bit stores)
    ulonglong2* dst = (ulonglong2*)(g_table + (size_t)t * 32);
    #pragma unroll
    for (int q = 0; q < 8; q++)
        dst[q] = make_ulonglong2(rad2[2 * q], rad2[2 * q + 1]);
}

// ---------------------------------------------------------------------------
// Fused per-node kernel. One warp per node; warp = 4 edge groups x 8 channel
// lanes. Slot payloads are loaded COALESCED once per 32-edge chunk and
// distributed by shuffle — the table lerp load is the only latency op per
// step.  acc[c][m]: c = channel (lane&7)*4+c, m = [aa, av*3, ad*6].
// ---------------------------------------------------------------------------
__global__ __launch_bounds__(128)
void node_kernel(const float* __restrict__ w_v, const float* __restrict__ w_d,
                 float* __restrict__ out, int N)
{
    __shared__ float s_wv[32 * 32];
    __shared__ float s_wd[32 * 32];
    __shared__ float s_t[4][32][9];

    for (int i = threadIdx.x; i < 32 * 32; i += blockDim.x) {
        s_wv[i] = w_v[i];
        s_wd[i] = w_d[i];
    }
    __syncthreads();

    int warp = threadIdx.x >> 5;
    int lane = threadIdx.x & 31;
    int g = lane >> 3;      // edge group 0..3
    int l = lane & 7;       // channel quarter 0..7
    int n = blockIdx.x * 4 + warp;
    if (n >= N) return;

    const float4* srs = g_slot_rs + (size_t)n * SLOTS;
    int cnt = g_count[n];
    if (cnt > SLOTS) cnt = SLOTS;

    float acc[4][10];
    #pragma unroll
    for (int c = 0; c < 4; c++)
        #pragma unroll
        for (int m = 0; m < 10; m++) acc[c][m] = 0.0f;

    for (int t0 = 0; t0 < cnt; t0 += 32) {
        // coalesced payload load; invalid lanes get clean zeros
        float4 myrs = (t0 + lane < cnt) ? __ldg(&srs[t0 + lane])
                                        : make_float4(0.f, 0.f, 0.f, 0.f);
        int rem = cnt - t0; if (rem > 32) rem = 32;
        int steps = (rem + 3) >> 2;
        #pragma unroll 4
        for (int i = 0; i < steps; i++) {
            int j = i * 4 + g;
            float u = __shfl_sync(0xffffffffu, myrs.w, j);
            float X = __shfl_sync(0xffffffffu, myrs.x, j);
            float Y = __shfl_sync(0xffffffffu, myrs.y, j);
            float Z = __shfl_sync(0xffffffffu, myrs.z, j);
            float wgt = (t0 + j < cnt) ? 1.0f : 0.0f;

            int idx = (int)u;
            if (idx > TABN - 2) idx = TABN - 2;
            float frac = u - (float)idx;
            const float4* rp = (const float4*)(g_table + (size_t)idx * 32) + l;
            float4 v0 = __ldg(rp);        // 4 x 128B rows / warp, L2-hot
            float4 v1 = __ldg(rp + 8);

            float ra[4];
            ra[0] = fmaf(frac, v1.x - v0.x, v0.x) * wgt;
            ra[1] = fmaf(frac, v1.y - v0.y, v0.y) * wgt;
            ra[2] = fmaf(frac, v1.z - v0.z, v0.z) * wgt;
            ra[3] = fmaf(frac, v1.w - v0.w, v0.w) * wgt;

            #pragma unroll
            for (int c = 0; c < 4; c++) {
                float r = ra[c];
                float tx = r * X, ty = r * Y, tz = r * Z;
                acc[c][0] += r;
                acc[c][1] += tx;  acc[c][2] += ty;  acc[c][3] += tz;
                acc[c][4] = fmaf(tx, X, acc[c][4]);   // XX
                acc[c][5] = fmaf(ty, Y, acc[c][5]);   // YY
                acc[c][6] = fmaf(tz, Z, acc[c][6]);   // ZZ
                acc[c][7] = fmaf(tx, Y, acc[c][7]);   // XY
                acc[c][8] = fmaf(tx, Z, acc[c][8]);   // XZ
                acc[c][9] = fmaf(ty, Z, acc[c][9]);   // YZ
            }
        }
    }

    // reduce across the 4 edge groups
    #pragma unroll
    for (int c = 0; c < 4; c++)
        #pragma unroll
        for (int m = 0; m < 10; m++) {
            acc[c][m] += __shfl_xor_sync(0xffffffffu, acc[c][m], 8);
            acc[c][m] += __shfl_xor_sync(0xffffffffu, acc[c][m], 16);
        }

    if (g == 0) {
        // A_a: channels l*4..l*4+3, contiguous float4 store
        float4 aav = make_float4(acc[0][0], acc[1][0], acc[2][0], acc[3][0]);
        *(float4*)(out + (size_t)n * 32 + l * 4) = aav;
        #pragma unroll
        for (int c = 0; c < 4; c++)
            #pragma unroll
            for (int m = 0; m < 9; m++)
                s_t[warp][l * 4 + c][m] = acc[c][m + 1];
    }
    __syncwarp();

    // lane = output channel
    float ov0 = 0.f, ov1 = 0.f, ov2 = 0.f;
    float od[6] = {0.f, 0.f, 0.f, 0.f, 0.f, 0.f};
    #pragma unroll
    for (int a = 0; a < 32; a++) {
        float wv = s_wv[a * 32 + lane];
        float wd = s_wd[a * 32 + lane];
        ov0 = fmaf(wv, s_t[warp][a][0], ov0);
        ov1 = fmaf(wv, s_t[warp][a][1], ov1);
        ov2 = fmaf(wv, s_t[warp][a][2], ov2);
        #pragma unroll
        for (int s = 0; s < 6; s++) od[s] = fmaf(wd, s_t[warp][a][3 + s], od[s]);
    }

    // out_v: [N][32][3] at offset N*32
    float* pv = out + (size_t)N * 32 + (size_t)n * 96 + lane * 3;
    pv[0] = ov0; pv[1] = ov1; pv[2] = ov2;

    // out_d: [N][32][3][3] at offset N*128 ; od = [XX,YY,ZZ,XY,XZ,YZ]
    float* pd = out + (size_t)N * 128 + (size_t)n * 288 + lane * 9;
    pd[0] = od[0]; pd[1] = od[3]; pd[2] = od[4];
    pd[3] = od[3]; pd[4] = od[1]; pd[5] = od[5];
    pd[6] = od[4]; pd[7] = od[5]; pd[8] = od[2];
}

// ---------------------------------------------------------------------------
// kernel_launch
// ---------------------------------------------------------------------------
extern "C" void kernel_launch(void* const* d_in, const int* in_sizes, int n_in,
                              void* d_out, int out_size) {
    const float* r_ij     = (const float*)d_in[0];
    const float* w_rad    = (const float*)d_in[1];
    const float* b_rad    = (const float*)d_in[2];
    const float* w_direct = (const float*)d_in[3];
    const float* w1       = (const float*)d_in[4];
    const float* b1       = (const float*)d_in[5];
    const float* w2       = (const float*)d_in[6];
    const float* b2       = (const float*)d_in[7];
    const float* w3       = (const float*)d_in[8];
    const float* b3       = (const float*)d_in[9];
    const float* w_v      = (const float*)d_in[10];
    const float* w_d      = (const float*)d_in[11];
    const int*   e_src    = (const int*)  d_in[12];

    int E = in_sizes[0] / 3;
    int N = out_size / 416;

    float* out = (float*)d_out;

    zero_counts_kernel<<<(N + 255) / 256, 256>>>(N);

    // Per-edge prep: payload (X,Y,Z,u) written straight into node slots
    prep_kernel<<<(E + 255) / 256, 256>>>(r_ij, e_src, E);

    // Radial-MLP lookup table (16384 samples)
    table_kernel<<<(TABN + 127) / 128, 128>>>(
        w_rad, b_rad, w_direct, w1, b1, w2, b2, w3, b3);

    // Fused gather + table interp + moments + contraction
    node_kernel<<<(N + 3) / 4, 128>>>(w_v, w_d, out, N);
}

// round 13
// speedup vs baseline: 16.9768x; 1.0753x over previous
#include <cuda_runtime.h>
#include <math.h>

#define MAX_NODES 20000
#define MAX_EDGES 640000
#define SLOTS     160          // padded per-node edge capacity (max degree ~66)
#define TABN      16384
#define DMAX      2.0f
#define TSCALE    8191.5f      // (TABN-1)/DMAX

// Static scratch (no allocation allowed).
__device__ float  g_table[TABN * 32];              // rad = F(d) lookup, 2MB (L2-hot)
__device__ int    g_count[MAX_NODES];
__device__ float4 g_slot_rs[MAX_NODES * SLOTS];    // per-slot payload (X,Y,Z,u)

// ---------------------------------------------------------------------------
// Packed f32x2 helpers (Blackwell — only reachable via PTX)
// ---------------------------------------------------------------------------
typedef unsigned long long u64;

__device__ __forceinline__ u64 pack2(float lo, float hi) {
    u64 r;
    asm("mov.b64 %0, {%1, %2};" : "=l"(r) : "f"(lo), "f"(hi));
    return r;
}
__device__ __forceinline__ void unpack2(u64 v, float& lo, float& hi) {
    asm("mov.b64 {%0, %1}, %2;" : "=f"(lo), "=f"(hi) : "l"(v));
}
#define FMA2(d, a, b, c) \
    asm("fma.rn.f32x2 %0, %1, %2, %3;" : "=l"(d) : "l"(a), "l"(b), "l"(c))
#define MUL2(d, a, b) \
    asm("mul.rn.f32x2 %0, %1, %2;" : "=l"(d) : "l"(a), "l"(b))
#define ADD2(d, a, b) \
    asm("add.rn.f32x2 %0, %1, %2;" : "=l"(d) : "l"(a), "l"(b))

// ---------------------------------------------------------------------------
// Zero the per-node counters.
// ---------------------------------------------------------------------------
__global__ void zero_counts_kernel(int N) {
    int i = blockIdx.x * blockDim.x + threadIdx.x;
    if (i < N) g_count[i] = 0;
}

// ---------------------------------------------------------------------------
// Per-edge prep: compute (X,Y,Z,u) and write it DIRECTLY into the node's
// slot list. u pre-clamped so the node kernel needs no idx clamp.
// ---------------------------------------------------------------------------
__global__ void prep_kernel(const float* __restrict__ r_ij,
                            const int* __restrict__ edges_src, int E) {
    int e = blockIdx.x * blockDim.x + threadIdx.x;
    if (e >= E) return;

    int n = edges_src[e];
    int slot = atomicAdd(&g_count[n], 1);

    float rx = r_ij[3 * e + 0];
    float ry = r_ij[3 * e + 1];
    float rz = r_ij[3 * e + 2];
    float d2 = rx * rx + ry * ry + rz * rz;
    float d  = sqrtf(d2);
    // rs = tens_sigmoid(r * 7): r*7 / sqrt(1 + 49*d2)
    float inv = rsqrtf(1.0f + 49.0f * d2) * 7.0f;
    float u = fminf(d * TSCALE, (float)(TABN - 1) - 0.5f);  // idx always <= TABN-2
    if (slot < SLOTS)
        g_slot_rs[n * SLOTS + slot] = make_float4(rx * inv, ry * inv, rz * inv, u);
}

// ---------------------------------------------------------------------------
// Table builder: rad = F(d) for TABN samples of d in [0, DMAX].
// Full radial MLP on packed f32x2 (one thread = one sample).
// ---------------------------------------------------------------------------
__global__ __launch_bounds__(128)
void table_kernel(const float* __restrict__ w_rad,  const float* __restrict__ b_rad,
                  const float* __restrict__ w_direct,
                  const float* __restrict__ w1, const float* __restrict__ b1,
                  const float* __restrict__ w2, const float* __restrict__ b2,
                  const float* __restrict__ w3, const float* __restrict__ b3)
{
    __shared__ __align__(16) float s_wrad[8 * 32];
    __shared__ __align__(16) float s_brad[32];
    __shared__ __align__(16) float s_wdir[32 * 32];
    __shared__ __align__(16) float s_w1[32 * 64];
    __shared__ __align__(16) float s_b1[64];
    __shared__ __align__(16) float s_w2[64 * 64];
    __shared__ __align__(16) float s_b2[64];
    __shared__ __align__(16) float s_w3[64 * 32];
    __shared__ __align__(16) float s_b3[32];

    for (int i = threadIdx.x; i < 8 * 32;  i += blockDim.x) s_wrad[i] = w_rad[i];
    for (int i = threadIdx.x; i < 32;      i += blockDim.x) s_brad[i] = b_rad[i];
    for (int i = threadIdx.x; i < 32 * 32; i += blockDim.x) s_wdir[i] = w_direct[i];
    for (int i = threadIdx.x; i < 32 * 64; i += blockDim.x) s_w1[i]   = w1[i];
    for (int i = threadIdx.x; i < 64;      i += blockDim.x) s_b1[i]   = b1[i];
    for (int i = threadIdx.x; i < 64 * 64; i += blockDim.x) s_w2[i]   = w2[i];
    for (int i = threadIdx.x; i < 64;      i += blockDim.x) s_b2[i]   = b2[i];
    for (int i = threadIdx.x; i < 64 * 32; i += blockDim.x) s_w3[i]   = w3[i];
    for (int i = threadIdx.x; i < 32;      i += blockDim.x) s_b3[i]   = b3[i];
    __syncthreads();

    int t = blockIdx.x * blockDim.x + threadIdx.x;
    if (t >= TABN) return;

    float d = (float)t * (DMAX / (float)(TABN - 1));

    // 8 Gaussian RBFs; centers k/7, width 1/8
    float enc[8];
    #pragma unroll
    for (int k = 0; k < 8; k++) {
        float x = (d - (float)k * (1.0f / 7.0f)) * 8.0f;
        enc[k] = __expf(-x * x);
    }

    const u64* W_RAD = (const u64*)s_wrad;
    const u64* B_RAD = (const u64*)s_brad;
    const u64* W_DIR = (const u64*)s_wdir;
    const u64* W_1   = (const u64*)s_w1;
    const u64* B_1   = (const u64*)s_b1;
    const u64* W_2   = (const u64*)s_w2;
    const u64* B_2   = (const u64*)s_b2;
    const u64* W_3   = (const u64*)s_w3;
    const u64* B_3   = (const u64*)s_b3;

    u64 h2[16];
    #pragma unroll
    for (int p = 0; p < 16; p++) h2[p] = B_RAD[p];
    #pragma unroll
    for (int k = 0; k < 8; k++) {
        u64 ek2 = pack2(enc[k], enc[k]);
        #pragma unroll
        for (int p = 0; p < 16; p++) FMA2(h2[p], ek2, W_RAD[k * 16 + p], h2[p]);
    }

    u64 rad2[16];
    #pragma unroll
    for (int p = 0; p < 16; p++) rad2[p] = 0;
    u64 t1[32];
    #pragma unroll
    for (int p = 0; p < 32; p++) t1[p] = B_1[p];

    #pragma unroll
    for (int kp = 0; kp < 16; kp++) {
        float hk0, hk1;
        unpack2(h2[kp], hk0, hk1);
        u64 a0 = pack2(hk0, hk0);
        u64 a1 = pack2(hk1, hk1);
        int k0 = 2 * kp, k1 = 2 * kp + 1;
        #pragma unroll
        for (int p = 0; p < 16; p++) {
            FMA2(rad2[p], a0, W_DIR[k0 * 16 + p], rad2[p]);
            FMA2(rad2[p], a1, W_DIR[k1 * 16 + p], rad2[p]);
        }
        #pragma unroll
        for (int p = 0; p < 32; p++) {
            FMA2(t1[p], a0, W_1[k0 * 32 + p], t1[p]);
            FMA2(t1[p], a1, W_1[k1 * 32 + p], t1[p]);
        }
    }
    #pragma unroll
    for (int p = 0; p < 32; p++) {
        float lo, hi;
        unpack2(t1[p], lo, hi);
        lo = fmaxf(lo, 0.1f * lo);
        hi = fmaxf(hi, 0.1f * hi);
        t1[p] = pack2(lo, hi);
    }

    u64 t2[32];
    #pragma unroll
    for (int p = 0; p < 32; p++) t2[p] = B_2[p];
    #pragma unroll
    for (int kp = 0; kp < 32; kp++) {
        float k0v, k1v;
        unpack2(t1[kp], k0v, k1v);
        u64 a0 = pack2(k0v, k0v);
        u64 a1 = pack2(k1v, k1v);
        int k0 = 2 * kp, k1 = 2 * kp + 1;
        #pragma unroll
        for (int p = 0; p < 32; p++) {
            FMA2(t2[p], a0, W_2[k0 * 32 + p], t2[p]);
            FMA2(t2[p], a1, W_2[k1 * 32 + p], t2[p]);
        }
    }
    #pragma unroll
    for (int p = 0; p < 32; p++) {
        float lo, hi;
        unpack2(t2[p], lo, hi);
        lo = fmaxf(lo, 0.1f * lo);
        hi = fmaxf(hi, 0.1f * hi);
        t2[p] = pack2(lo, hi);
    }

    u64 one2 = pack2(1.0f, 1.0f);
    #pragma unroll
    for (int p = 0; p < 16; p++) FMA2(rad2[p], one2, B_3[p], rad2[p]);
    #pragma unroll
    for (int kp = 0; kp < 32; kp++) {
        float k0v, k1v;
        unpack2(t2[kp], k0v, k1v);
        u64 a0 = pack2(k0v, k0v);
        u64 a1 = pack2(k1v, k1v);
        int k0 = 2 * kp, k1 = 2 * kp + 1;
        #pragma unroll
        for (int p = 0; p < 16; p++) {
            FMA2(rad2[p], a0, W_3[k0 * 16 + p], rad2[p]);
            FMA2(rad2[p], a1, W_3[k1 * 16 + p], rad2[p]);
        }
    }

    // store table row (128-bit stores)
    ulonglong2* dst = (ulonglong2*)(g_table + (size_t)t * 32);
    #pragma unroll
    for (int q = 0; q < 8; q++)
        dst[q] = make_ulonglong2(rad2[2 * q], rad2[2 * q + 1]);
}

// ---------------------------------------------------------------------------
// Moment accumulation for one edge on 2 packed channel pairs.
// acc2[p][m]: p = channel pair, m = [aa, avX, avY, avZ, XX, YY, ZZ, XY, XZ, YZ]
// ---------------------------------------------------------------------------
__device__ __forceinline__ void accum_pair(u64 acc2[10], u64 r, u64 X2, u64 Y2, u64 Z2) {
    u64 tx, ty, tz;
    MUL2(tx, r, X2); MUL2(ty, r, Y2); MUL2(tz, r, Z2);
    ADD2(acc2[0], acc2[0], r);
    ADD2(acc2[1], acc2[1], tx);
    ADD2(acc2[2], acc2[2], ty);
    ADD2(acc2[3], acc2[3], tz);
    FMA2(acc2[4], tx, X2, acc2[4]);
    FMA2(acc2[5], ty, Y2, acc2[5]);
    FMA2(acc2[6], tz, Z2, acc2[6]);
    FMA2(acc2[7], tx, Y2, acc2[7]);
    FMA2(acc2[8], tx, Z2, acc2[8]);
    FMA2(acc2[9], ty, Z2, acc2[9]);
}

// ---------------------------------------------------------------------------
// Fused per-node kernel. One warp per node; warp = 4 edge groups x 8 channel
// lanes; per step 4 edges in flight (float4 table loads), all moment math in
// packed f32x2. Main loop is mask-free; chunk tail handled separately.
// ---------------------------------------------------------------------------
__global__ __launch_bounds__(128)
void node_kernel(const float* __restrict__ w_v, const float* __restrict__ w_d,
                 float* __restrict__ out, int N)
{
    __shared__ float s_wv[32 * 32];
    __shared__ float s_wd[32 * 32];
    __shared__ float s_t[4][32][9];

    for (int i = threadIdx.x; i < 32 * 32; i += blockDim.x) {
        s_wv[i] = w_v[i];
        s_wd[i] = w_d[i];
    }
    __syncthreads();

    int warp = threadIdx.x >> 5;
    int lane = threadIdx.x & 31;
    int g = lane >> 3;      // edge group 0..3
    int l = lane & 7;       // channel quarter 0..7 (channels l*4 .. l*4+3)
    int n = blockIdx.x * 4 + warp;
    if (n >= N) return;

    const float4* srs = g_slot_rs + (size_t)n * SLOTS;
    int cnt = g_count[n];
    if (cnt > SLOTS) cnt = SLOTS;

    u64 acc2[2][10];
    #pragma unroll
    for (int p = 0; p < 2; p++)
        #pragma unroll
        for (int m = 0; m < 10; m++) acc2[p][m] = 0;

    for (int t0 = 0; t0 < cnt; t0 += 32) {
        float4 myrs = (t0 + lane < cnt) ? __ldg(&srs[t0 + lane])
                                        : make_float4(0.f, 0.f, 0.f, 0.f);
        int rem = cnt - t0; if (rem > 32) rem = 32;
        int full = rem >> 2;              // steps where all 4 groups are valid

        #pragma unroll 4
        for (int i = 0; i < full; i++) {
            int j = i * 4 + g;
            float u = __shfl_sync(0xffffffffu, myrs.w, j);
            float X = __shfl_sync(0xffffffffu, myrs.x, j);
            float Y = __shfl_sync(0xffffffffu, myrs.y, j);
            float Z = __shfl_sync(0xffffffffu, myrs.z, j);

            int idx = (int)u;
            float frac = u - (float)idx;
            const float4* rp = (const float4*)(g_table + (size_t)idx * 32) + l;
            float4 v0 = __ldg(rp);
            float4 v1 = __ldg(rp + 8);

            u64 fr2 = pack2(frac, frac);
            float om = 1.0f - frac;
            u64 om2 = pack2(om, om);
            u64 X2 = pack2(X, X), Y2 = pack2(Y, Y), Z2 = pack2(Z, Z);

            u64 v0a = pack2(v0.x, v0.y), v0b = pack2(v0.z, v0.w);
            u64 v1a = pack2(v1.x, v1.y), v1b = pack2(v1.z, v1.w);
            u64 ta, tb, ra, rb;
            MUL2(ta, v1a, fr2);  FMA2(ra, v0a, om2, ta);
            MUL2(tb, v1b, fr2);  FMA2(rb, v0b, om2, tb);

            accum_pair(acc2[0], ra, X2, Y2, Z2);
            accum_pair(acc2[1], rb, X2, Y2, Z2);
        }

        if (rem & 3) {  // masked tail step
            int j = full * 4 + g;
            float u = __shfl_sync(0xffffffffu, myrs.w, j);
            float X = __shfl_sync(0xffffffffu, myrs.x, j);
            float Y = __shfl_sync(0xffffffffu, myrs.y, j);
            float Z = __shfl_sync(0xffffffffu, myrs.z, j);
            float wgt = (j < rem) ? 1.0f : 0.0f;

            int idx = (int)u;
            float frac = u - (float)idx;
            const float4* rp = (const float4*)(g_table + (size_t)idx * 32) + l;
            float4 v0 = __ldg(rp);
            float4 v1 = __ldg(rp + 8);

            u64 fr2 = pack2(frac * wgt, frac * wgt);
            float om = (1.0f - frac) * wgt;
            u64 om2 = pack2(om, om);
            u64 X2 = pack2(X, X), Y2 = pack2(Y, Y), Z2 = pack2(Z, Z);

            u64 v0a = pack2(v0.x, v0.y), v0b = pack2(v0.z, v0.w);
            u64 v1a = pack2(v1.x, v1.y), v1b = pack2(v1.z, v1.w);
            u64 ta, tb, ra, rb;
            MUL2(ta, v1a, fr2);  FMA2(ra, v0a, om2, ta);
            MUL2(tb, v1b, fr2);  FMA2(rb, v0b, om2, tb);

            accum_pair(acc2[0], ra, X2, Y2, Z2);
            accum_pair(acc2[1], rb, X2, Y2, Z2);
        }
    }

    // unpack to scalars: acc[c][m] for channels c = 0..3 of this lane
    float acc[4][10];
    #pragma unroll
    for (int m = 0; m < 10; m++) {
        unpack2(acc2[0][m], acc[0][m], acc[1][m]);
        unpack2(acc2[1][m], acc[2][m], acc[3][m]);
    }

    // reduce across the 4 edge groups
    #pragma unroll
    for (int c = 0; c < 4; c++)
        #pragma unroll
        for (int m = 0; m < 10; m++) {
            acc[c][m] += __shfl_xor_sync(0xffffffffu, acc[c][m], 8);
            acc[c][m] += __shfl_xor_sync(0xffffffffu, acc[c][m], 16);
        }

    if (g == 0) {
        // A_a: channels l*4..l*4+3, contiguous float4 store
        float4 aav = make_float4(acc[0][0], acc[1][0], acc[2][0], acc[3][0]);
        *(float4*)(out + (size_t)n * 32 + l * 4) = aav;
        #pragma unroll
        for (int c = 0; c < 4; c++)
            #pragma unroll
            for (int m = 0; m < 9; m++)
                s_t[warp][l * 4 + c][m] = acc[c][m + 1];
    }
    __syncwarp();

    // lane = output channel
    float ov0 = 0.f, ov1 = 0.f, ov2 = 0.f;
    float od[6] = {0.f, 0.f, 0.f, 0.f, 0.f, 0.f};
    #pragma unroll
    for (int a = 0; a < 32; a++) {
        float wv = s_wv[a * 32 + lane];
        float wd = s_wd[a * 32 + lane];
        ov0 = fmaf(wv, s_t[warp][a][0], ov0);
        ov1 = fmaf(wv, s_t[warp][a][1], ov1);
        ov2 = fmaf(wv, s_t[warp][a][2], ov2);
        #pragma unroll
        for (int s = 0; s < 6; s++) od[s] = fmaf(wd, s_t[warp][a][3 + s], od[s]);
    }

    // out_v: [N][32][3] at offset N*32
    float* pv = out + (size_t)N * 32 + (size_t)n * 96 + lane * 3;
    pv[0] = ov0; pv[1] = ov1; pv[2] = ov2;

    // out_d: [N][32][3][3] at offset N*128 ; od = [XX,YY,ZZ,XY,XZ,YZ]
    float* pd = out + (size_t)N * 128 + (size_t)n * 288 + lane * 9;
    pd[0] = od[0]; pd[1] = od[3]; pd[2] = od[4];
    pd[3] = od[3]; pd[4] = od[1]; pd[5] = od[5];
    pd[6] = od[4]; pd[7] = od[5]; pd[8] = od[2];
}

// ---------------------------------------------------------------------------
// kernel_launch
// ---------------------------------------------------------------------------
extern "C" void kernel_launch(void* const* d_in, const int* in_sizes, int n_in,
                              void* d_out, int out_size) {
    const float* r_ij     = (const float*)d_in[0];
    const float* w_rad    = (const float*)d_in[1];
    const float* b_rad    = (const float*)d_in[2];
    const float* w_direct = (const float*)d_in[3];
    const float* w1       = (const float*)d_in[4];
    const float* b1       = (const float*)d_in[5];
    const float* w2       = (const float*)d_in[6];
    const float* b2       = (const float*)d_in[7];
    const float* w3       = (const float*)d_in[8];
    const float* b3       = (const float*)d_in[9];
    const float* w_v      = (const float*)d_in[10];
    const float* w_d      = (const float*)d_in[11];
    const int*   e_src    = (const int*)  d_in[12];

    int E = in_sizes[0] / 3;
    int N = out_size / 416;

    float* out = (float*)d_out;

    zero_counts_kernel<<<(N + 255) / 256, 256>>>(N);

    // Per-edge prep: payload (X,Y,Z,u) written straight into node slots
    prep_kernel<<<(E + 255) / 256, 256>>>(r_ij, e_src, E);

    // Radial-MLP lookup table (16384 samples)
    table_kernel<<<(TABN + 127) / 128, 128>>>(
        w_rad, b_rad, w_direct, w1, b1, w2, b2, w3, b3);

    // Fused gather + table interp + moments + contraction
    node_kernel<<<(N + 3) / 4, 128>>>(w_v, w_d, out, N);
}